// round 2
// baseline (speedup 1.0000x reference)
#include <cuda_runtime.h>

#define Nn 4096
#define Ee 262144
#define FIN 512
#define HID 64
#define NH 8
#define NC 16
#define LALPHA 0.2f

// ---------------- scratch (static __device__, no allocations) ----------------
__device__ unsigned g_bitmap[Nn * Nn / 32];   // 2MB dedup bitmap
__device__ int g_deg[Nn];
__device__ int g_rowptr[Nn + 1];
__device__ int g_cursor[Nn];
__device__ unsigned char g_keep[Ee];
__device__ int g_col[Ee];
__device__ float g_h1[Nn * 512];              // layer1 h, heads concat on cols (8MB)
__device__ float g_x[Nn * 512];               // elu(att@h + b) concat (8MB)
__device__ float g_s1[NH * Nn];
__device__ float g_s2[NH * Nn];
__device__ float g_colsum1[512];
__device__ float g_h2[Nn * NC];
__device__ float g_t1[Nn];
__device__ float g_t2[Nn];
__device__ float g_colsum2[NC];

// ---------------- helpers ----------------
__device__ __forceinline__ float wredsum(float v) {
    #pragma unroll
    for (int o = 16; o; o >>= 1) v += __shfl_xor_sync(0xffffffffu, v, o);
    return v;
}
__device__ __forceinline__ float wredmax(float v) {
    #pragma unroll
    for (int o = 16; o; o >>= 1) v = fmaxf(v, __shfl_xor_sync(0xffffffffu, v, o));
    return v;
}

// ---------------- graph build ----------------
__global__ void k_clear() {
    int i = blockIdx.x * blockDim.x + threadIdx.x;
    if (i < Nn * Nn / 32) g_bitmap[i] = 0u;
    if (i < Nn) g_deg[i] = 0;
    if (i < 512) g_colsum1[i] = 0.f;
    if (i < NC) g_colsum2[i] = 0.f;
}

__global__ void k_dedup(const int* __restrict__ el) {
    int e = blockIdx.x * blockDim.x + threadIdx.x;
    if (e >= Ee) return;
    int s = el[e];
    int t = el[Ee + e];
    unsigned idx = ((unsigned)s << 12) | (unsigned)t;
    unsigned m = 1u << (idx & 31);
    unsigned old = atomicOr(&g_bitmap[idx >> 5], m);
    bool isnew = !(old & m);
    g_keep[e] = isnew ? 1 : 0;
    if (isnew) atomicAdd(&g_deg[s], 1);
}

__global__ void k_scan() {   // 1 block, 1024 threads, 4 elems/thread
    __shared__ int sh[1024];
    int tid = threadIdx.x;
    int v0 = g_deg[4 * tid + 0];
    int v1 = g_deg[4 * tid + 1];
    int v2 = g_deg[4 * tid + 2];
    int v3 = g_deg[4 * tid + 3];
    int tot = v0 + v1 + v2 + v3;
    sh[tid] = tot;
    __syncthreads();
    for (int off = 1; off < 1024; off <<= 1) {
        int t = (tid >= off) ? sh[tid - off] : 0;
        __syncthreads();
        sh[tid] += t;
        __syncthreads();
    }
    int p = sh[tid] - tot;   // exclusive prefix
    g_rowptr[4 * tid + 0] = p; g_cursor[4 * tid + 0] = p; p += v0;
    g_rowptr[4 * tid + 1] = p; g_cursor[4 * tid + 1] = p; p += v1;
    g_rowptr[4 * tid + 2] = p; g_cursor[4 * tid + 2] = p; p += v2;
    g_rowptr[4 * tid + 3] = p; g_cursor[4 * tid + 3] = p; p += v3;
    if (tid == 1023) g_rowptr[Nn] = sh[1023];
}

__global__ void k_scatter(const int* __restrict__ el) {
    int e = blockIdx.x * blockDim.x + threadIdx.x;
    if (e >= Ee) return;
    if (g_keep[e]) {
        int s = el[e];
        int t = el[Ee + e];
        int pos = atomicAdd(&g_cursor[s], 1);
        g_col[pos] = t;
    }
}

// ---------------- GEMM1: h1 = features @ Wcat  (Wcat[k][h*64+j] = W_heads[h][k][j]) --
// 128x128 tile, BK=8, 256 threads, 8x8 per thread
__global__ void k_gemm1(const float* __restrict__ A, const float* __restrict__ Wh) {
    __shared__ float As[8][128];
    __shared__ float Bs[8][128];
    int tid = threadIdx.x;
    int tx = tid & 15, ty = tid >> 4;
    int row0 = blockIdx.y * 128, col0 = blockIdx.x * 128;
    int arow = tid >> 1, ak4 = (tid & 1) * 4;
    int bk = tid >> 5, bc = (tid & 31) * 4;
    float acc[8][8];
    #pragma unroll
    for (int i = 0; i < 8; i++)
        #pragma unroll
        for (int j = 0; j < 8; j++) acc[i][j] = 0.f;

    for (int k0 = 0; k0 < FIN; k0 += 8) {
        float4 av = *(const float4*)(A + (row0 + arow) * FIN + k0 + ak4);
        As[ak4 + 0][arow] = av.x; As[ak4 + 1][arow] = av.y;
        As[ak4 + 2][arow] = av.z; As[ak4 + 3][arow] = av.w;
        int c = col0 + bc;
        int head = c >> 6;
        const float* bp = Wh + head * (FIN * HID) + (k0 + bk) * HID + (c & 63);
        *(float4*)&Bs[bk][bc] = *(const float4*)bp;
        __syncthreads();
        #pragma unroll
        for (int k = 0; k < 8; k++) {
            float af[8], bf[8];
            *(float4*)(af)     = *(float4*)&As[k][ty * 4];
            *(float4*)(af + 4) = *(float4*)&As[k][64 + ty * 4];
            *(float4*)(bf)     = *(float4*)&Bs[k][tx * 4];
            *(float4*)(bf + 4) = *(float4*)&Bs[k][64 + tx * 4];
            #pragma unroll
            for (int i = 0; i < 8; i++)
                #pragma unroll
                for (int j = 0; j < 8; j++)
                    acc[i][j] = fmaf(af[i], bf[j], acc[i][j]);
        }
        __syncthreads();
    }
    #pragma unroll
    for (int i = 0; i < 8; i++) {
        int r = row0 + ((i < 4) ? (ty * 4 + i) : (64 + ty * 4 + (i - 4)));
        *(float4*)(g_h1 + r * 512 + col0 + tx * 4) =
            make_float4(acc[i][0], acc[i][1], acc[i][2], acc[i][3]);
        *(float4*)(g_h1 + r * 512 + col0 + 64 + tx * 4) =
            make_float4(acc[i][4], acc[i][5], acc[i][6], acc[i][7]);
    }
}

// ---------------- per-node attention score halves, layer 1 ----------------
__global__ void k_scores1(const float* __restrict__ a_heads) {
    int n = blockIdx.x;
    int h = threadIdx.x >> 5, lane = threadIdx.x & 31;
    const float* hp = g_h1 + n * 512 + h * HID;
    float v0 = hp[lane], v1 = hp[lane + 32];
    const float* ap = a_heads + h * 2 * HID;
    float p1 = v0 * ap[lane] + v1 * ap[lane + 32];
    float p2 = v0 * ap[64 + lane] + v1 * ap[96 + lane];
    p1 = wredsum(p1);
    p2 = wredsum(p2);
    if (lane == 0) {
        g_s1[h * Nn + n] = p1;
        g_s2[h * Nn + n] = p2;
    }
}

__global__ void k_colmean1() {   // grid 64, block 512
    int c = threadIdx.x;
    int r0 = blockIdx.x * 64;
    float s = 0.f;
    #pragma unroll 4
    for (int r = 0; r < 64; r++) s += g_h1[(r0 + r) * 512 + c];
    atomicAdd(&g_colsum1[c], s);
}

// ---------------- layer-1 softmax aggregation (+bias +elu) ----------------
__global__ void k_agg1(const float* __restrict__ b_heads) {
    int i = blockIdx.x;
    int h = threadIdx.x >> 5, lane = threadIdx.x & 31;
    int p0 = g_rowptr[i], p1 = g_rowptr[i + 1];
    float o0, o1;
    if (p0 == p1) {
        o0 = g_colsum1[h * HID + lane] * (1.f / Nn);
        o1 = g_colsum1[h * HID + lane + 32] * (1.f / Nn);
    } else {
        float s1i = g_s1[h * Nn + i];
        const float* s2p = g_s2 + h * Nn;
        float m = -1e30f;
        for (int p = p0 + lane; p < p1; p += 32) {
            float e = s1i + s2p[g_col[p]];
            e = e > 0.f ? e : LALPHA * e;
            m = fmaxf(m, e);
        }
        m = wredmax(m);
        float ss = 0.f;
        for (int p = p0 + lane; p < p1; p += 32) {
            float e = s1i + s2p[g_col[p]];
            e = e > 0.f ? e : LALPHA * e;
            ss += expf(e - m);
        }
        ss = wredsum(ss);
        float inv = 1.f / ss;
        float a0 = 0.f, a1 = 0.f;
        const float* hb = g_h1 + h * HID + lane;
        for (int p = p0; p < p1; p++) {
            int t = g_col[p];
            float e = s1i + s2p[t];
            e = e > 0.f ? e : LALPHA * e;
            float w = expf(e - m) * inv;
            a0 = fmaf(w, hb[t * 512], a0);
            a1 = fmaf(w, hb[t * 512 + 32], a1);
        }
        o0 = a0; o1 = a1;
    }
    o0 += b_heads[h * HID + lane];
    o1 += b_heads[h * HID + lane + 32];
    o0 = o0 > 0.f ? o0 : expm1f(o0);   // elu
    o1 = o1 > 0.f ? o1 : expm1f(o1);
    g_x[i * 512 + h * HID + lane] = o0;
    g_x[i * 512 + h * HID + lane + 32] = o1;
}

// ---------------- GEMM2: h2 = x @ W_out [512,16] ----------------
__global__ void k_gemm2(const float* __restrict__ Wout) {
    __shared__ float Ws[512 * NC];
    int tid = threadIdx.x;
    for (int j = tid; j < 512 * NC; j += 256) Ws[j] = Wout[j];
    __syncthreads();
    int col = tid & 15, rs = tid >> 4;
    int row = blockIdx.x * 16 + rs;
    const float* xp = g_x + row * 512;
    float a0 = 0.f, a1 = 0.f, a2 = 0.f, a3 = 0.f;
    #pragma unroll 4
    for (int k = 0; k < 512; k += 4) {
        a0 = fmaf(xp[k + 0], Ws[(k + 0) * NC + col], a0);
        a1 = fmaf(xp[k + 1], Ws[(k + 1) * NC + col], a1);
        a2 = fmaf(xp[k + 2], Ws[(k + 2) * NC + col], a2);
        a3 = fmaf(xp[k + 3], Ws[(k + 3) * NC + col], a3);
    }
    g_h2[row * NC + col] = (a0 + a1) + (a2 + a3);
}

// ---------------- layer-2 scores + column sum ----------------
__global__ void k_scores2(const float* __restrict__ a_out) {
    int wid = threadIdx.x >> 5, lane = threadIdx.x & 31;
    int n = blockIdx.x * 8 + wid;
    float v  = (lane < 16) ? g_h2[n * NC + lane] : 0.f;
    float q1 = (lane < 16) ? v * a_out[lane] : 0.f;
    float q2 = (lane < 16) ? v * a_out[16 + lane] : 0.f;
    #pragma unroll
    for (int o = 8; o; o >>= 1) {
        q1 += __shfl_xor_sync(0xffffffffu, q1, o);
        q2 += __shfl_xor_sync(0xffffffffu, q2, o);
    }
    if (lane == 0) { g_t1[n] = q1; g_t2[n] = q2; }
    if (lane < 16) atomicAdd(&g_colsum2[lane], v);
}

// ---------------- layer-2 aggregation + log_softmax ----------------
__global__ void k_agg2(const float* __restrict__ b_out, float* __restrict__ out) {
    int wid = threadIdx.x >> 5, lane = threadIdx.x & 31;
    int i = blockIdx.x * 8 + wid;
    int p0 = g_rowptr[i], p1 = g_rowptr[i + 1];
    float logit = 0.f;
    if (p0 == p1) {
        if (lane < 16) logit = g_colsum2[lane] * (1.f / Nn) + b_out[lane];
    } else {
        float t1i = g_t1[i];
        float m = -1e30f;
        for (int p = p0 + lane; p < p1; p += 32) {
            float e = t1i + g_t2[g_col[p]];
            e = e > 0.f ? e : LALPHA * e;
            m = fmaxf(m, e);
        }
        m = wredmax(m);
        float ss = 0.f;
        for (int p = p0 + lane; p < p1; p += 32) {
            float e = t1i + g_t2[g_col[p]];
            e = e > 0.f ? e : LALPHA * e;
            ss += expf(e - m);
        }
        ss = wredsum(ss);
        float inv = 1.f / ss;
        float acc = 0.f;
        for (int p = p0; p < p1; p++) {
            int t = g_col[p];
            float e = t1i + g_t2[t];
            e = e > 0.f ? e : LALPHA * e;
            float w = expf(e - m) * inv;
            if (lane < 16) acc = fmaf(w, g_h2[t * NC + lane], acc);
        }
        if (lane < 16) logit = acc + b_out[lane];
    }
    // log_softmax over 16 classes
    float lm = (lane < 16) ? logit : -1e30f;
    #pragma unroll
    for (int o = 8; o; o >>= 1) lm = fmaxf(lm, __shfl_xor_sync(0xffffffffu, lm, o));
    float es = (lane < 16) ? expf(logit - lm) : 0.f;
    #pragma unroll
    for (int o = 8; o; o >>= 1) es += __shfl_xor_sync(0xffffffffu, es, o);
    if (lane < 16) out[i * NC + lane] = logit - lm - logf(es);
}

// ---------------- launch ----------------
extern "C" void kernel_launch(void* const* d_in, const int* in_sizes, int n_in,
                              void* d_out, int out_size) {
    const float* features    = (const float*)d_in[0];
    const int* el            = (const int*)d_in[1];
    const float* W_heads     = (const float*)d_in[2];
    const float* a_heads     = (const float*)d_in[3];
    const float* b_heads     = (const float*)d_in[4];
    const float* W_out       = (const float*)d_in[5];
    const float* a_out       = (const float*)d_in[6];
    const float* b_out       = (const float*)d_in[7];
    float* out = (float*)d_out;

    k_clear<<<(Nn * Nn / 32 + 255) / 256, 256>>>();
    k_dedup<<<Ee / 256, 256>>>(el);
    k_scan<<<1, 1024>>>();
    k_scatter<<<Ee / 256, 256>>>(el);
    k_gemm1<<<dim3(4, 32), 256>>>(features, W_heads);
    k_scores1<<<Nn, 256>>>(a_heads);
    k_colmean1<<<64, 512>>>();
    k_agg1<<<Nn, 256>>>(b_heads);
    k_gemm2<<<Nn / 16, 256>>>(W_out);
    k_scores2<<<Nn / 8, 256>>>(a_out);
    k_agg2<<<Nn / 8, 256>>>(b_out, out);
}

// round 3
// speedup vs baseline: 1.2148x; 1.2148x over previous
#include <cuda_runtime.h>
#include <cuda_fp16.h>

#define Nn 4096
#define Ee 262144
#define FIN 512
#define HID 64
#define NH 8
#define NC 16
#define LALPHA 0.2f

// ---------------- scratch (static __device__, no allocations) ----------------
__device__ unsigned g_bitmap[Nn * Nn / 32];   // 2MB dedup bitmap
__device__ int g_deg[Nn];
__device__ int g_rowptr[Nn + 1];
__device__ int g_cursor[Nn];
__device__ unsigned char g_keep[Ee];
__device__ int g_col[Ee];
__device__ float g_h1[Nn * 512];              // layer1 h, heads concat on cols (8MB)
__device__ float g_x[Nn * 512];               // elu(att@h + b) concat (8MB)
__device__ float g_s1[NH * Nn];
__device__ float g_s2[NH * Nn];
__device__ float g_colsum1[512];
__device__ float g_h2[Nn * NC];
__device__ float g_t1[Nn];
__device__ float g_t2[Nn];
__device__ float g_colsum2[NC];

// ---------------- helpers ----------------
__device__ __forceinline__ float wredsum(float v) {
    #pragma unroll
    for (int o = 16; o; o >>= 1) v += __shfl_xor_sync(0xffffffffu, v, o);
    return v;
}
__device__ __forceinline__ float wredmax(float v) {
    #pragma unroll
    for (int o = 16; o; o >>= 1) v = fmaxf(v, __shfl_xor_sync(0xffffffffu, v, o));
    return v;
}

__device__ __forceinline__ void ldm_x4(unsigned* r, const void* p) {
    unsigned a = (unsigned)__cvta_generic_to_shared(p);
    asm volatile("ldmatrix.sync.aligned.m8n8.x4.shared.b16 {%0,%1,%2,%3}, [%4];"
        : "=r"(r[0]), "=r"(r[1]), "=r"(r[2]), "=r"(r[3]) : "r"(a));
}
__device__ __forceinline__ void ldm_x2t(unsigned* r, const void* p) {
    unsigned a = (unsigned)__cvta_generic_to_shared(p);
    asm volatile("ldmatrix.sync.aligned.m8n8.x2.trans.shared.b16 {%0,%1}, [%2];"
        : "=r"(r[0]), "=r"(r[1]) : "r"(a));
}
__device__ __forceinline__ void mma16816(float* c, const unsigned* a, const unsigned* b) {
    asm volatile("mma.sync.aligned.m16n8k16.row.col.f32.f16.f16.f32 "
        "{%0,%1,%2,%3}, {%4,%5,%6,%7}, {%8,%9}, {%0,%1,%2,%3};"
        : "+f"(c[0]), "+f"(c[1]), "+f"(c[2]), "+f"(c[3])
        : "r"(a[0]), "r"(a[1]), "r"(a[2]), "r"(a[3]), "r"(b[0]), "r"(b[1]));
}

// ---------------- graph build ----------------
__global__ void k_clear() {
    int i = blockIdx.x * blockDim.x + threadIdx.x;
    if (i < Nn * Nn / 128) ((uint4*)g_bitmap)[i] = make_uint4(0, 0, 0, 0);
    if (i < Nn) g_deg[i] = 0;
    if (i < 512) g_colsum1[i] = 0.f;
    if (i < NC) g_colsum2[i] = 0.f;
}

__global__ void k_dedup(const int* __restrict__ el) {
    int e = blockIdx.x * blockDim.x + threadIdx.x;
    if (e >= Ee) return;
    int s = el[e];
    int t = el[Ee + e];
    unsigned idx = ((unsigned)s << 12) | (unsigned)t;
    unsigned m = 1u << (idx & 31);
    unsigned old = atomicOr(&g_bitmap[idx >> 5], m);
    bool isnew = !(old & m);
    g_keep[e] = isnew ? 1 : 0;
    if (isnew) atomicAdd(&g_deg[s], 1);
}

__global__ void k_scan() {   // 1 block, 1024 threads, 4 elems/thread
    __shared__ int sh[1024];
    int tid = threadIdx.x;
    int v0 = g_deg[4 * tid + 0];
    int v1 = g_deg[4 * tid + 1];
    int v2 = g_deg[4 * tid + 2];
    int v3 = g_deg[4 * tid + 3];
    int tot = v0 + v1 + v2 + v3;
    sh[tid] = tot;
    __syncthreads();
    for (int off = 1; off < 1024; off <<= 1) {
        int t = (tid >= off) ? sh[tid - off] : 0;
        __syncthreads();
        sh[tid] += t;
        __syncthreads();
    }
    int p = sh[tid] - tot;   // exclusive prefix
    g_rowptr[4 * tid + 0] = p; g_cursor[4 * tid + 0] = p; p += v0;
    g_rowptr[4 * tid + 1] = p; g_cursor[4 * tid + 1] = p; p += v1;
    g_rowptr[4 * tid + 2] = p; g_cursor[4 * tid + 2] = p; p += v2;
    g_rowptr[4 * tid + 3] = p; g_cursor[4 * tid + 3] = p; p += v3;
    if (tid == 1023) g_rowptr[Nn] = sh[1023];
}

__global__ void k_scatter(const int* __restrict__ el) {
    int e = blockIdx.x * blockDim.x + threadIdx.x;
    if (e >= Ee) return;
    if (g_keep[e]) {
        int s = el[e];
        int t = el[Ee + e];
        int pos = atomicAdd(&g_cursor[s], 1);
        g_col[pos] = t;
    }
}

// ---------------- GEMM1 via fp16 tensor cores, 3-term split precision -------
// h1 = features @ Wcat,  Wcat[k][h*64+j] = W_heads[h][k][j]
#define BM 128
#define BN 128
#define BK 32
#define LDA 40    // halves per As row (32 + 8 pad): conflict-free ldmatrix
#define LDB 136   // halves per Bs row (128 + 8 pad)

__global__ void __launch_bounds__(256) k_gemm1_mma(
        const float* __restrict__ A, const float* __restrict__ Wh) {
    __shared__ __half As_hi[BM][LDA], As_lo[BM][LDA];
    __shared__ __half Bs_hi[BK][LDB], Bs_lo[BK][LDB];
    int tid = threadIdx.x;
    int wid = tid >> 5, lane = tid & 31;
    int wm = wid & 1, wn = wid >> 1;          // warp tile: 64x32
    int row0 = blockIdx.y * BM, col0 = blockIdx.x * BN;

    int arow = tid >> 1, acol = (tid & 1) * 16;   // 16 floats of A per thread
    int bkrow = tid >> 3, bn = (tid & 7) * 16;    // 16 floats of B per thread
    int head = (col0 + bn) >> 6;
    const float* aptr = A + (row0 + arow) * FIN + acol;
    const float* bptr = Wh + head * (FIN * HID) + bkrow * HID + ((col0 + bn) & 63);

    float areg[16], breg[16];
    #pragma unroll
    for (int i = 0; i < 4; i++) *(float4*)(areg + 4 * i) = *(const float4*)(aptr + 4 * i);
    #pragma unroll
    for (int i = 0; i < 4; i++) *(float4*)(breg + 4 * i) = *(const float4*)(bptr + 4 * i);

    float acc[4][4][4];
    #pragma unroll
    for (int mi = 0; mi < 4; mi++)
        #pragma unroll
        for (int ni = 0; ni < 4; ni++)
            #pragma unroll
            for (int q = 0; q < 4; q++) acc[mi][ni][q] = 0.f;

    for (int k0 = 0; k0 < FIN; k0 += BK) {
        // convert + store current tile (half2 stores)
        #pragma unroll
        for (int i = 0; i < 16; i += 2) {
            __half h0 = __float2half_rn(areg[i]);
            __half h1v = __float2half_rn(areg[i + 1]);
            __half l0 = __float2half_rn(areg[i] - __half2float(h0));
            __half l1 = __float2half_rn(areg[i + 1] - __half2float(h1v));
            *(__half2*)&As_hi[arow][acol + i] = __halves2half2(h0, h1v);
            *(__half2*)&As_lo[arow][acol + i] = __halves2half2(l0, l1);
            __half g0 = __float2half_rn(breg[i]);
            __half g1 = __float2half_rn(breg[i + 1]);
            __half m0 = __float2half_rn(breg[i] - __half2float(g0));
            __half m1 = __float2half_rn(breg[i + 1] - __half2float(g1));
            *(__half2*)&Bs_hi[bkrow][bn + i] = __halves2half2(g0, g1);
            *(__half2*)&Bs_lo[bkrow][bn + i] = __halves2half2(m0, m1);
        }
        __syncthreads();
        if (k0 + BK < FIN) {   // prefetch next tile into registers
            #pragma unroll
            for (int i = 0; i < 4; i++)
                *(float4*)(areg + 4 * i) = *(const float4*)(aptr + (k0 + BK) + 4 * i);
            #pragma unroll
            for (int i = 0; i < 4; i++)
                *(float4*)(breg + 4 * i) = *(const float4*)(bptr + (k0 + BK) * HID + 4 * i);
        }
        #pragma unroll
        for (int ks = 0; ks < BK; ks += 16) {
            unsigned afh[4][4], afl[4][4], bfh[4][2], bfl[4][2];
            #pragma unroll
            for (int mi = 0; mi < 4; mi++) {
                int r = wm * 64 + mi * 16 + (lane & 15);
                int c = ks + (lane >> 4) * 8;
                ldm_x4(afh[mi], &As_hi[r][c]);
                ldm_x4(afl[mi], &As_lo[r][c]);
            }
            #pragma unroll
            for (int ni = 0; ni < 4; ni++) {
                int kr = ks + (lane & 15);
                int nc = wn * 32 + ni * 8;
                ldm_x2t(bfh[ni], &Bs_hi[kr][nc]);
                ldm_x2t(bfl[ni], &Bs_lo[kr][nc]);
            }
            #pragma unroll
            for (int mi = 0; mi < 4; mi++)
                #pragma unroll
                for (int ni = 0; ni < 4; ni++) {
                    mma16816(acc[mi][ni], afh[mi], bfh[ni]);
                    mma16816(acc[mi][ni], afh[mi], bfl[ni]);
                    mma16816(acc[mi][ni], afl[mi], bfh[ni]);
                }
        }
        __syncthreads();
    }
    #pragma unroll
    for (int mi = 0; mi < 4; mi++)
        #pragma unroll
        for (int ni = 0; ni < 4; ni++) {
            int r = row0 + wm * 64 + mi * 16 + (lane >> 2);
            int c = col0 + wn * 32 + ni * 8 + (lane & 3) * 2;
            *(float2*)(g_h1 + r * 512 + c) = make_float2(acc[mi][ni][0], acc[mi][ni][1]);
            *(float2*)(g_h1 + (r + 8) * 512 + c) = make_float2(acc[mi][ni][2], acc[mi][ni][3]);
        }
}

// ---------------- per-node attention score halves, layer 1 ----------------
__global__ void k_scores1(const float* __restrict__ a_heads) {
    int n = blockIdx.x;
    int h = threadIdx.x >> 5, lane = threadIdx.x & 31;
    const float* hp = g_h1 + n * 512 + h * HID;
    float v0 = hp[lane], v1 = hp[lane + 32];
    const float* ap = a_heads + h * 2 * HID;
    float p1 = v0 * ap[lane] + v1 * ap[lane + 32];
    float p2 = v0 * ap[64 + lane] + v1 * ap[96 + lane];
    p1 = wredsum(p1);
    p2 = wredsum(p2);
    if (lane == 0) {
        g_s1[h * Nn + n] = p1;
        g_s2[h * Nn + n] = p2;
    }
}

__global__ void k_colmean1() {   // grid 64, block 512
    int c = threadIdx.x;
    int r0 = blockIdx.x * 64;
    float s = 0.f;
    #pragma unroll 4
    for (int r = 0; r < 64; r++) s += g_h1[(r0 + r) * 512 + c];
    atomicAdd(&g_colsum1[c], s);
}

// ---------------- layer-1 softmax aggregation (+bias +elu) ----------------
__global__ void k_agg1(const float* __restrict__ b_heads) {
    int i = blockIdx.x;
    int h = threadIdx.x >> 5, lane = threadIdx.x & 31;
    int p0 = g_rowptr[i], p1 = g_rowptr[i + 1];
    float o0, o1;
    if (p0 == p1) {
        o0 = g_colsum1[h * HID + lane] * (1.f / Nn);
        o1 = g_colsum1[h * HID + lane + 32] * (1.f / Nn);
    } else {
        float s1i = g_s1[h * Nn + i];
        const float* s2p = g_s2 + h * Nn;
        float m = -1e30f;
        for (int p = p0 + lane; p < p1; p += 32) {
            float e = s1i + s2p[g_col[p]];
            e = e > 0.f ? e : LALPHA * e;
            m = fmaxf(m, e);
        }
        m = wredmax(m);
        float ss = 0.f;
        for (int p = p0 + lane; p < p1; p += 32) {
            float e = s1i + s2p[g_col[p]];
            e = e > 0.f ? e : LALPHA * e;
            ss += expf(e - m);
        }
        ss = wredsum(ss);
        float inv = 1.f / ss;
        float a0 = 0.f, a1 = 0.f;
        const float* hb = g_h1 + h * HID + lane;
        for (int p = p0; p < p1; p++) {
            int t = g_col[p];
            float e = s1i + s2p[t];
            e = e > 0.f ? e : LALPHA * e;
            float w = expf(e - m) * inv;
            a0 = fmaf(w, hb[t * 512], a0);
            a1 = fmaf(w, hb[t * 512 + 32], a1);
        }
        o0 = a0; o1 = a1;
    }
    o0 += b_heads[h * HID + lane];
    o1 += b_heads[h * HID + lane + 32];
    o0 = o0 > 0.f ? o0 : expm1f(o0);   // elu
    o1 = o1 > 0.f ? o1 : expm1f(o1);
    g_x[i * 512 + h * HID + lane] = o0;
    g_x[i * 512 + h * HID + lane + 32] = o1;
}

// ---------------- GEMM2: h2 = x @ W_out [512,16] ----------------
__global__ void k_gemm2(const float* __restrict__ Wout) {
    __shared__ float Ws[512 * NC];
    int tid = threadIdx.x;
    for (int j = tid; j < 512 * NC; j += 256) Ws[j] = Wout[j];
    __syncthreads();
    int col = tid & 15, rs = tid >> 4;
    int row = blockIdx.x * 16 + rs;
    const float* xp = g_x + row * 512;
    float a0 = 0.f, a1 = 0.f, a2 = 0.f, a3 = 0.f;
    #pragma unroll 4
    for (int k = 0; k < 512; k += 4) {
        a0 = fmaf(xp[k + 0], Ws[(k + 0) * NC + col], a0);
        a1 = fmaf(xp[k + 1], Ws[(k + 1) * NC + col], a1);
        a2 = fmaf(xp[k + 2], Ws[(k + 2) * NC + col], a2);
        a3 = fmaf(xp[k + 3], Ws[(k + 3) * NC + col], a3);
    }
    g_h2[row * NC + col] = (a0 + a1) + (a2 + a3);
}

// ---------------- layer-2 scores + column sum ----------------
__global__ void k_scores2(const float* __restrict__ a_out) {
    int wid = threadIdx.x >> 5, lane = threadIdx.x & 31;
    int n = blockIdx.x * 8 + wid;
    float v  = (lane < 16) ? g_h2[n * NC + lane] : 0.f;
    float q1 = (lane < 16) ? v * a_out[lane] : 0.f;
    float q2 = (lane < 16) ? v * a_out[16 + lane] : 0.f;
    #pragma unroll
    for (int o = 8; o; o >>= 1) {
        q1 += __shfl_xor_sync(0xffffffffu, q1, o);
        q2 += __shfl_xor_sync(0xffffffffu, q2, o);
    }
    if (lane == 0) { g_t1[n] = q1; g_t2[n] = q2; }
    if (lane < 16) atomicAdd(&g_colsum2[lane], v);
}

// ---------------- layer-2 aggregation + log_softmax ----------------
__global__ void k_agg2(const float* __restrict__ b_out, float* __restrict__ out) {
    int wid = threadIdx.x >> 5, lane = threadIdx.x & 31;
    int i = blockIdx.x * 8 + wid;
    int p0 = g_rowptr[i], p1 = g_rowptr[i + 1];
    float logit = 0.f;
    if (p0 == p1) {
        if (lane < 16) logit = g_colsum2[lane] * (1.f / Nn) + b_out[lane];
    } else {
        float t1i = g_t1[i];
        float m = -1e30f;
        for (int p = p0 + lane; p < p1; p += 32) {
            float e = t1i + g_t2[g_col[p]];
            e = e > 0.f ? e : LALPHA * e;
            m = fmaxf(m, e);
        }
        m = wredmax(m);
        float ss = 0.f;
        for (int p = p0 + lane; p < p1; p += 32) {
            float e = t1i + g_t2[g_col[p]];
            e = e > 0.f ? e : LALPHA * e;
            ss += expf(e - m);
        }
        ss = wredsum(ss);
        float inv = 1.f / ss;
        float acc = 0.f;
        for (int p = p0; p < p1; p++) {
            int t = g_col[p];
            float e = t1i + g_t2[t];
            e = e > 0.f ? e : LALPHA * e;
            float w = expf(e - m) * inv;
            if (lane < 16) acc = fmaf(w, g_h2[t * NC + lane], acc);
        }
        if (lane < 16) logit = acc + b_out[lane];
    }
    // log_softmax over 16 classes
    float lm = (lane < 16) ? logit : -1e30f;
    #pragma unroll
    for (int o = 8; o; o >>= 1) lm = fmaxf(lm, __shfl_xor_sync(0xffffffffu, lm, o));
    float es = (lane < 16) ? expf(logit - lm) : 0.f;
    #pragma unroll
    for (int o = 8; o; o >>= 1) es += __shfl_xor_sync(0xffffffffu, es, o);
    if (lane < 16) out[i * NC + lane] = logit - lm - logf(es);
}

// ---------------- launch ----------------
extern "C" void kernel_launch(void* const* d_in, const int* in_sizes, int n_in,
                              void* d_out, int out_size) {
    const float* features    = (const float*)d_in[0];
    const int* el            = (const int*)d_in[1];
    const float* W_heads     = (const float*)d_in[2];
    const float* a_heads     = (const float*)d_in[3];
    const float* b_heads     = (const float*)d_in[4];
    const float* W_out       = (const float*)d_in[5];
    const float* a_out       = (const float*)d_in[6];
    const float* b_out       = (const float*)d_in[7];
    float* out = (float*)d_out;

    k_clear<<<(Nn * Nn / 128 + 255) / 256, 256>>>();
    k_dedup<<<Ee / 256, 256>>>(el);
    k_scan<<<1, 1024>>>();
    k_scatter<<<Ee / 256, 256>>>(el);
    k_gemm1_mma<<<dim3(4, 32), 256>>>(features, W_heads);
    k_scores1<<<Nn, 256>>>(a_heads);
    k_colmean1<<<64, 512>>>();
    k_agg1<<<Nn, 256>>>(b_heads);
    k_gemm2<<<Nn / 16, 256>>>(W_out);
    k_scores2<<<Nn / 8, 256>>>(a_out);
    k_agg2<<<Nn / 8, 256>>>(b_out, out);
}

// round 4
// speedup vs baseline: 1.6144x; 1.3289x over previous
#include <cuda_runtime.h>
#include <cuda_fp16.h>

#define Nn 4096
#define Ee 262144
#define FIN 512
#define HID 64
#define NH 8
#define NC 16
#define LALPHA 0.2f

// ---------------- scratch (static __device__, no allocations) ----------------
__device__ unsigned g_bitmap[Nn * Nn / 32];   // 2MB dedup bitmap
__device__ int g_deg[Nn];
__device__ int g_rowptr[Nn + 1];
__device__ int g_cursor[Nn];
__device__ unsigned char g_keep[Ee];
__device__ int g_col[Ee];
__device__ float g_h1[Nn * 512];              // layer1 h fp32 (8MB)
__device__ __half g_h1h[Nn * 512];            // layer1 h fp16 (4MB) for aggregation
__device__ float g_x[Nn * 512];               // elu(att@h + b) concat (8MB)
__device__ float g_s1[NH * Nn];
__device__ float g_s2[NH * Nn];
__device__ float g_colsum1[512];
__device__ float g_h2[Nn * NC];
__device__ float g_t1[Nn];
__device__ float g_t2[Nn];
__device__ float g_colsum2[NC];

// ---------------- helpers ----------------
__device__ __forceinline__ float wredsum(float v) {
    #pragma unroll
    for (int o = 16; o; o >>= 1) v += __shfl_xor_sync(0xffffffffu, v, o);
    return v;
}
__device__ __forceinline__ float wredmax(float v) {
    #pragma unroll
    for (int o = 16; o; o >>= 1) v = fmaxf(v, __shfl_xor_sync(0xffffffffu, v, o));
    return v;
}

__device__ __forceinline__ void ldm_x4(unsigned* r, const void* p) {
    unsigned a = (unsigned)__cvta_generic_to_shared(p);
    asm volatile("ldmatrix.sync.aligned.m8n8.x4.shared.b16 {%0,%1,%2,%3}, [%4];"
        : "=r"(r[0]), "=r"(r[1]), "=r"(r[2]), "=r"(r[3]) : "r"(a));
}
__device__ __forceinline__ void ldm_x2t(unsigned* r, const void* p) {
    unsigned a = (unsigned)__cvta_generic_to_shared(p);
    asm volatile("ldmatrix.sync.aligned.m8n8.x2.trans.shared.b16 {%0,%1}, [%2];"
        : "=r"(r[0]), "=r"(r[1]) : "r"(a));
}
__device__ __forceinline__ void mma16816(float* c, const unsigned* a, const unsigned* b) {
    asm volatile("mma.sync.aligned.m16n8k16.row.col.f32.f16.f16.f32 "
        "{%0,%1,%2,%3}, {%4,%5,%6,%7}, {%8,%9}, {%0,%1,%2,%3};"
        : "+f"(c[0]), "+f"(c[1]), "+f"(c[2]), "+f"(c[3])
        : "r"(a[0]), "r"(a[1]), "r"(a[2]), "r"(a[3]), "r"(b[0]), "r"(b[1]));
}

// ---------------- graph build ----------------
__global__ void k_clear() {
    int i = blockIdx.x * blockDim.x + threadIdx.x;
    if (i < Nn * Nn / 128) ((uint4*)g_bitmap)[i] = make_uint4(0, 0, 0, 0);
    if (i < Nn) g_deg[i] = 0;
    if (i < 512) g_colsum1[i] = 0.f;
    if (i < NC) g_colsum2[i] = 0.f;
}

__global__ void k_dedup(const int* __restrict__ el) {   // 4 edges/thread for MLP
    int b = 4 * (blockIdx.x * blockDim.x + threadIdx.x);
    if (b >= Ee) return;
    int4 sv = *(const int4*)(el + b);
    int4 tv = *(const int4*)(el + Ee + b);
    int ss[4] = {sv.x, sv.y, sv.z, sv.w};
    int tt[4] = {tv.x, tv.y, tv.z, tv.w};
    unsigned old[4];
    #pragma unroll
    for (int q = 0; q < 4; q++) {
        unsigned idx = ((unsigned)ss[q] << 12) | (unsigned)tt[q];
        old[q] = atomicOr(&g_bitmap[idx >> 5], 1u << (idx & 31));
    }
    uchar4 kp;
    unsigned char* kpp = (unsigned char*)&kp;
    #pragma unroll
    for (int q = 0; q < 4; q++) {
        unsigned idx = ((unsigned)ss[q] << 12) | (unsigned)tt[q];
        bool isnew = !(old[q] & (1u << (idx & 31)));
        kpp[q] = isnew ? 1 : 0;
        if (isnew) atomicAdd(&g_deg[ss[q]], 1);
    }
    *(uchar4*)(g_keep + b) = kp;
}

__global__ void k_scan() {   // 1 block, 1024 threads, 4 elems/thread
    __shared__ int sh[1024];
    int tid = threadIdx.x;
    int v0 = g_deg[4 * tid + 0];
    int v1 = g_deg[4 * tid + 1];
    int v2 = g_deg[4 * tid + 2];
    int v3 = g_deg[4 * tid + 3];
    int tot = v0 + v1 + v2 + v3;
    sh[tid] = tot;
    __syncthreads();
    for (int off = 1; off < 1024; off <<= 1) {
        int t = (tid >= off) ? sh[tid - off] : 0;
        __syncthreads();
        sh[tid] += t;
        __syncthreads();
    }
    int p = sh[tid] - tot;   // exclusive prefix
    g_rowptr[4 * tid + 0] = p; g_cursor[4 * tid + 0] = p; p += v0;
    g_rowptr[4 * tid + 1] = p; g_cursor[4 * tid + 1] = p; p += v1;
    g_rowptr[4 * tid + 2] = p; g_cursor[4 * tid + 2] = p; p += v2;
    g_rowptr[4 * tid + 3] = p; g_cursor[4 * tid + 3] = p; p += v3;
    if (tid == 1023) g_rowptr[Nn] = sh[1023];
}

__global__ void k_scatter(const int* __restrict__ el) {  // 4 edges/thread
    int b = 4 * (blockIdx.x * blockDim.x + threadIdx.x);
    if (b >= Ee) return;
    int4 sv = *(const int4*)(el + b);
    int4 tv = *(const int4*)(el + Ee + b);
    uchar4 kp = *(const uchar4*)(g_keep + b);
    int ss[4] = {sv.x, sv.y, sv.z, sv.w};
    int tt[4] = {tv.x, tv.y, tv.z, tv.w};
    unsigned char kk[4] = {kp.x, kp.y, kp.z, kp.w};
    int pos[4];
    #pragma unroll
    for (int q = 0; q < 4; q++)
        pos[q] = kk[q] ? atomicAdd(&g_cursor[ss[q]], 1) : -1;
    #pragma unroll
    for (int q = 0; q < 4; q++)
        if (kk[q]) g_col[pos[q]] = tt[q];
}

// ---------------- GEMM1 via fp16 tensor cores, 3-term split precision -------
#define BM 128
#define BN 128
#define BK 32
#define LDA 40
#define LDB 136

__global__ void __launch_bounds__(256) k_gemm1_mma(
        const float* __restrict__ A, const float* __restrict__ Wh) {
    __shared__ __half As_hi[BM][LDA], As_lo[BM][LDA];
    __shared__ __half Bs_hi[BK][LDB], Bs_lo[BK][LDB];
    int tid = threadIdx.x;
    int wid = tid >> 5, lane = tid & 31;
    int wm = wid & 1, wn = wid >> 1;          // warp tile: 64x32
    int row0 = blockIdx.y * BM, col0 = blockIdx.x * BN;

    int arow = tid >> 1, acol = (tid & 1) * 16;
    int bkrow = tid >> 3, bn = (tid & 7) * 16;
    int head = (col0 + bn) >> 6;
    const float* aptr = A + (row0 + arow) * FIN + acol;
    const float* bptr = Wh + head * (FIN * HID) + bkrow * HID + ((col0 + bn) & 63);

    float areg[16], breg[16];
    #pragma unroll
    for (int i = 0; i < 4; i++) *(float4*)(areg + 4 * i) = *(const float4*)(aptr + 4 * i);
    #pragma unroll
    for (int i = 0; i < 4; i++) *(float4*)(breg + 4 * i) = *(const float4*)(bptr + 4 * i);

    float acc[4][4][4];
    #pragma unroll
    for (int mi = 0; mi < 4; mi++)
        #pragma unroll
        for (int ni = 0; ni < 4; ni++)
            #pragma unroll
            for (int q = 0; q < 4; q++) acc[mi][ni][q] = 0.f;

    for (int k0 = 0; k0 < FIN; k0 += BK) {
        #pragma unroll
        for (int i = 0; i < 16; i += 2) {
            __half h0 = __float2half_rn(areg[i]);
            __half h1v = __float2half_rn(areg[i + 1]);
            __half l0 = __float2half_rn(areg[i] - __half2float(h0));
            __half l1 = __float2half_rn(areg[i + 1] - __half2float(h1v));
            *(__half2*)&As_hi[arow][acol + i] = __halves2half2(h0, h1v);
            *(__half2*)&As_lo[arow][acol + i] = __halves2half2(l0, l1);
            __half g0 = __float2half_rn(breg[i]);
            __half g1 = __float2half_rn(breg[i + 1]);
            __half m0 = __float2half_rn(breg[i] - __half2float(g0));
            __half m1 = __float2half_rn(breg[i + 1] - __half2float(g1));
            *(__half2*)&Bs_hi[bkrow][bn + i] = __halves2half2(g0, g1);
            *(__half2*)&Bs_lo[bkrow][bn + i] = __halves2half2(m0, m1);
        }
        __syncthreads();
        if (k0 + BK < FIN) {
            #pragma unroll
            for (int i = 0; i < 4; i++)
                *(float4*)(areg + 4 * i) = *(const float4*)(aptr + (k0 + BK) + 4 * i);
            #pragma unroll
            for (int i = 0; i < 4; i++)
                *(float4*)(breg + 4 * i) = *(const float4*)(bptr + (k0 + BK) * HID + 4 * i);
        }
        #pragma unroll
        for (int ks = 0; ks < BK; ks += 16) {
            unsigned afh[4][4], afl[4][4], bfh[4][2], bfl[4][2];
            #pragma unroll
            for (int mi = 0; mi < 4; mi++) {
                int r = wm * 64 + mi * 16 + (lane & 15);
                int c = ks + (lane >> 4) * 8;
                ldm_x4(afh[mi], &As_hi[r][c]);
                ldm_x4(afl[mi], &As_lo[r][c]);
            }
            #pragma unroll
            for (int ni = 0; ni < 4; ni++) {
                int kr = ks + (lane & 15);
                int nc = wn * 32 + ni * 8;
                ldm_x2t(bfh[ni], &Bs_hi[kr][nc]);
                ldm_x2t(bfl[ni], &Bs_lo[kr][nc]);
            }
            #pragma unroll
            for (int mi = 0; mi < 4; mi++)
                #pragma unroll
                for (int ni = 0; ni < 4; ni++) {
                    mma16816(acc[mi][ni], afh[mi], bfh[ni]);
                    mma16816(acc[mi][ni], afh[mi], bfl[ni]);
                    mma16816(acc[mi][ni], afl[mi], bfh[ni]);
                }
        }
        __syncthreads();
    }
    #pragma unroll
    for (int mi = 0; mi < 4; mi++)
        #pragma unroll
        for (int ni = 0; ni < 4; ni++) {
            int r = row0 + wm * 64 + mi * 16 + (lane >> 2);
            int c = col0 + wn * 32 + ni * 8 + (lane & 3) * 2;
            *(float2*)(g_h1 + r * 512 + c) = make_float2(acc[mi][ni][0], acc[mi][ni][1]);
            *(float2*)(g_h1 + (r + 8) * 512 + c) = make_float2(acc[mi][ni][2], acc[mi][ni][3]);
            *(__half2*)(g_h1h + r * 512 + c) =
                __floats2half2_rn(acc[mi][ni][0], acc[mi][ni][1]);
            *(__half2*)(g_h1h + (r + 8) * 512 + c) =
                __floats2half2_rn(acc[mi][ni][2], acc[mi][ni][3]);
        }
}

// ---------------- per-node attention score halves, layer 1 ----------------
__global__ void k_scores1(const float* __restrict__ a_heads) {
    int n = blockIdx.x;
    int h = threadIdx.x >> 5, lane = threadIdx.x & 31;
    const float* hp = g_h1 + n * 512 + h * HID;
    float v0 = hp[lane], v1 = hp[lane + 32];
    const float* ap = a_heads + h * 2 * HID;
    float p1 = v0 * ap[lane] + v1 * ap[lane + 32];
    float p2 = v0 * ap[64 + lane] + v1 * ap[96 + lane];
    p1 = wredsum(p1);
    p2 = wredsum(p2);
    if (lane == 0) {
        g_s1[h * Nn + n] = p1;
        g_s2[h * Nn + n] = p2;
    }
}

__global__ void k_colmean1() {   // grid 64, block 512
    int c = threadIdx.x;
    int r0 = blockIdx.x * 64;
    float s = 0.f;
    #pragma unroll 4
    for (int r = 0; r < 64; r++) s += g_h1[(r0 + r) * 512 + c];
    atomicAdd(&g_colsum1[c], s);
}

// ---------------- layer-1 softmax aggregation (+bias +elu) ----------------
// block = 256 (8 warps = 8 heads), one node per block. Lane owns 2 ADJACENT cols.
__global__ void __launch_bounds__(256) k_agg1(const float* __restrict__ b_heads) {
    __shared__ float wbuf[8][132];
    __shared__ int   cbuf[8][132];
    int i = blockIdx.x;
    int h = threadIdx.x >> 5, lane = threadIdx.x & 31;
    int p0 = g_rowptr[i], p1 = g_rowptr[i + 1];
    int deg = p1 - p0;
    int c0 = h * HID + 2 * lane;
    float o0, o1;
    if (deg == 0) {
        o0 = g_colsum1[c0] * (1.f / Nn);
        o1 = g_colsum1[c0 + 1] * (1.f / Nn);
    } else if (deg <= 128) {
        float s1i = g_s1[h * Nn + i];
        const float* s2p = g_s2 + h * Nn;
        float m = -1e30f;
        for (int j = lane; j < deg; j += 32) {
            int t = g_col[p0 + j];
            cbuf[h][j] = t;
            float e = s1i + s2p[t];
            e = e > 0.f ? e : LALPHA * e;
            wbuf[h][j] = e;
            m = fmaxf(m, e);
        }
        m = wredmax(m);
        float ss = 0.f;
        for (int j = lane; j < deg; j += 32) {
            float w = expf(wbuf[h][j] - m);
            wbuf[h][j] = w;
            ss += w;
        }
        ss = wredsum(ss);
        __syncwarp();
        float inv = 1.f / ss;
        float a0 = 0.f, a1 = 0.f;
        const int pair = h * 32 + lane;   // half2 index within a node row
        #pragma unroll 4
        for (int j = 0; j < deg; j++) {
            int t = cbuf[h][j];
            float w = wbuf[h][j];
            float2 v = __half22float2(*((const __half2*)(g_h1h + t * 512) + pair));
            a0 = fmaf(w, v.x, a0);
            a1 = fmaf(w, v.y, a1);
        }
        o0 = a0 * inv; o1 = a1 * inv;
    } else {   // rare fallback
        float s1i = g_s1[h * Nn + i];
        const float* s2p = g_s2 + h * Nn;
        float m = -1e30f;
        for (int p = p0 + lane; p < p1; p += 32) {
            float e = s1i + s2p[g_col[p]];
            e = e > 0.f ? e : LALPHA * e;
            m = fmaxf(m, e);
        }
        m = wredmax(m);
        float ss = 0.f;
        for (int p = p0 + lane; p < p1; p += 32) {
            float e = s1i + s2p[g_col[p]];
            e = e > 0.f ? e : LALPHA * e;
            ss += expf(e - m);
        }
        ss = wredsum(ss);
        float inv = 1.f / ss;
        float a0 = 0.f, a1 = 0.f;
        const int pair = h * 32 + lane;
        for (int p = p0; p < p1; p++) {
            int t = g_col[p];
            float e = s1i + s2p[t];
            e = e > 0.f ? e : LALPHA * e;
            float w = expf(e - m) * inv;
            float2 v = __half22float2(*((const __half2*)(g_h1h + t * 512) + pair));
            a0 = fmaf(w, v.x, a0);
            a1 = fmaf(w, v.y, a1);
        }
        o0 = a0; o1 = a1;
    }
    o0 += b_heads[c0];
    o1 += b_heads[c0 + 1];
    o0 = o0 > 0.f ? o0 : expm1f(o0);   // elu
    o1 = o1 > 0.f ? o1 : expm1f(o1);
    g_x[i * 512 + c0] = o0;
    g_x[i * 512 + c0 + 1] = o1;
}

// ---------------- GEMM2: h2 = x @ W_out [512,16] ----------------
__global__ void k_gemm2(const float* __restrict__ Wout) {
    __shared__ float Ws[512 * NC];
    int tid = threadIdx.x;
    for (int j = tid; j < 512 * NC; j += 256) Ws[j] = Wout[j];
    __syncthreads();
    int col = tid & 15, rs = tid >> 4;
    int row = blockIdx.x * 16 + rs;
    const float* xp = g_x + row * 512;
    float a0 = 0.f, a1 = 0.f, a2 = 0.f, a3 = 0.f;
    #pragma unroll 4
    for (int k = 0; k < 512; k += 4) {
        a0 = fmaf(xp[k + 0], Ws[(k + 0) * NC + col], a0);
        a1 = fmaf(xp[k + 1], Ws[(k + 1) * NC + col], a1);
        a2 = fmaf(xp[k + 2], Ws[(k + 2) * NC + col], a2);
        a3 = fmaf(xp[k + 3], Ws[(k + 3) * NC + col], a3);
    }
    g_h2[row * NC + col] = (a0 + a1) + (a2 + a3);
}

// ---------------- layer-2 scores + column sum ----------------
__global__ void k_scores2(const float* __restrict__ a_out) {
    int wid = threadIdx.x >> 5, lane = threadIdx.x & 31;
    int n = blockIdx.x * 8 + wid;
    float v  = (lane < 16) ? g_h2[n * NC + lane] : 0.f;
    float q1 = (lane < 16) ? v * a_out[lane] : 0.f;
    float q2 = (lane < 16) ? v * a_out[16 + lane] : 0.f;
    #pragma unroll
    for (int o = 8; o; o >>= 1) {
        q1 += __shfl_xor_sync(0xffffffffu, q1, o);
        q2 += __shfl_xor_sync(0xffffffffu, q2, o);
    }
    if (lane == 0) { g_t1[n] = q1; g_t2[n] = q2; }
    if (lane < 16) atomicAdd(&g_colsum2[lane], v);
}

// ---------------- layer-2 aggregation + log_softmax ----------------
__global__ void __launch_bounds__(256) k_agg2(const float* __restrict__ b_out,
                                              float* __restrict__ out) {
    __shared__ float wbuf[8][132];
    __shared__ int   cbuf[8][132];
    int wid = threadIdx.x >> 5, lane = threadIdx.x & 31;
    int i = blockIdx.x * 8 + wid;
    int p0 = g_rowptr[i], p1 = g_rowptr[i + 1];
    int deg = p1 - p0;
    float logit = 0.f;
    if (deg == 0) {
        if (lane < 16) logit = g_colsum2[lane] * (1.f / Nn) + b_out[lane];
    } else if (deg <= 128) {
        float t1i = g_t1[i];
        float m = -1e30f;
        for (int j = lane; j < deg; j += 32) {
            int t = g_col[p0 + j];
            cbuf[wid][j] = t;
            float e = t1i + g_t2[t];
            e = e > 0.f ? e : LALPHA * e;
            wbuf[wid][j] = e;
            m = fmaxf(m, e);
        }
        m = wredmax(m);
        float ss = 0.f;
        for (int j = lane; j < deg; j += 32) {
            float w = expf(wbuf[wid][j] - m);
            wbuf[wid][j] = w;
            ss += w;
        }
        ss = wredsum(ss);
        __syncwarp();
        float inv = 1.f / ss;
        float acc = 0.f;
        #pragma unroll 4
        for (int j = 0; j < deg; j++) {
            int t = cbuf[wid][j];
            float w = wbuf[wid][j];
            if (lane < 16) acc = fmaf(w, g_h2[t * NC + lane], acc);
        }
        if (lane < 16) logit = acc * inv + b_out[lane];
    } else {
        float t1i = g_t1[i];
        float m = -1e30f;
        for (int p = p0 + lane; p < p1; p += 32) {
            float e = t1i + g_t2[g_col[p]];
            e = e > 0.f ? e : LALPHA * e;
            m = fmaxf(m, e);
        }
        m = wredmax(m);
        float ss = 0.f;
        for (int p = p0 + lane; p < p1; p += 32) {
            float e = t1i + g_t2[g_col[p]];
            e = e > 0.f ? e : LALPHA * e;
            ss += expf(e - m);
        }
        ss = wredsum(ss);
        float inv = 1.f / ss;
        float acc = 0.f;
        for (int p = p0; p < p1; p++) {
            int t = g_col[p];
            float e = t1i + g_t2[t];
            e = e > 0.f ? e : LALPHA * e;
            float w = expf(e - m) * inv;
            if (lane < 16) acc = fmaf(w, g_h2[t * NC + lane], acc);
        }
        if (lane < 16) logit = acc + b_out[lane];
    }
    // log_softmax over 16 classes
    float lm = (lane < 16) ? logit : -1e30f;
    #pragma unroll
    for (int o = 8; o; o >>= 1) lm = fmaxf(lm, __shfl_xor_sync(0xffffffffu, lm, o));
    float es = (lane < 16) ? expf(logit - lm) : 0.f;
    #pragma unroll
    for (int o = 8; o; o >>= 1) es += __shfl_xor_sync(0xffffffffu, es, o);
    if (lane < 16) out[i * NC + lane] = logit - lm - logf(es);
}

// ---------------- launch ----------------
extern "C" void kernel_launch(void* const* d_in, const int* in_sizes, int n_in,
                              void* d_out, int out_size) {
    const float* features    = (const float*)d_in[0];
    const int* el            = (const int*)d_in[1];
    const float* W_heads     = (const float*)d_in[2];
    const float* a_heads     = (const float*)d_in[3];
    const float* b_heads     = (const float*)d_in[4];
    const float* W_out       = (const float*)d_in[5];
    const float* a_out       = (const float*)d_in[6];
    const float* b_out       = (const float*)d_in[7];
    float* out = (float*)d_out;

    k_clear<<<(Nn * Nn / 128 + 255) / 256, 256>>>();
    k_dedup<<<Ee / 1024, 256>>>(el);
    k_scan<<<1, 1024>>>();
    k_scatter<<<Ee / 1024, 256>>>(el);
    k_gemm1_mma<<<dim3(4, 32), 256>>>(features, W_heads);
    k_scores1<<<Nn, 256>>>(a_heads);
    k_colmean1<<<64, 512>>>();
    k_agg1<<<Nn, 256>>>(b_heads);
    k_gemm2<<<Nn / 16, 256>>>(W_out);
    k_scores2<<<Nn / 8, 256>>>(a_out);
    k_agg2<<<Nn / 8, 256>>>(b_out, out);
}

// round 5
// speedup vs baseline: 1.8261x; 1.1311x over previous
#include <cuda_runtime.h>
#include <cuda_fp16.h>

#define Nn 4096
#define Ee 262144
#define FIN 512
#define HID 64
#define NH 8
#define NC 16
#define LALPHA 0.2f

// ---------------- scratch (static __device__, no allocations) ----------------
__device__ unsigned g_bitmap[Nn * Nn / 32];   // 2MB dedup bitmap
__device__ int g_deg[Nn];
__device__ int g_rowptr[Nn + 1];
__device__ int g_rnk[Ee];                     // rank+1 within row, 0 = duplicate
__device__ int g_col[Ee];
__device__ __half g_Ahi[Nn * FIN], g_Alo[Nn * FIN];     // pre-split features
__device__ __half g_Whi[FIN * 512], g_Wlo[FIN * 512];   // pre-split Wcat
__device__ __half g_h1h[Nn * 512];            // layer1 h fp16 (4MB)
__device__ float g_x[Nn * 512];               // elu(att@h + b) concat (8MB)
__device__ float g_s1[NH * Nn];
__device__ float g_s2[NH * Nn];
__device__ float g_colsum1[512];
__device__ float g_h2[Nn * NC];
__device__ float g_t1[Nn];
__device__ float g_t2[Nn];
__device__ float g_colsum2[NC];

// ---------------- helpers ----------------
__device__ __forceinline__ float wredsum(float v) {
    #pragma unroll
    for (int o = 16; o; o >>= 1) v += __shfl_xor_sync(0xffffffffu, v, o);
    return v;
}
__device__ __forceinline__ float wredmax(float v) {
    #pragma unroll
    for (int o = 16; o; o >>= 1) v = fmaxf(v, __shfl_xor_sync(0xffffffffu, v, o));
    return v;
}

__device__ __forceinline__ void ldm_x4(unsigned* r, const void* p) {
    unsigned a = (unsigned)__cvta_generic_to_shared(p);
    asm volatile("ldmatrix.sync.aligned.m8n8.x4.shared.b16 {%0,%1,%2,%3}, [%4];"
        : "=r"(r[0]), "=r"(r[1]), "=r"(r[2]), "=r"(r[3]) : "r"(a));
}
__device__ __forceinline__ void ldm_x2t(unsigned* r, const void* p) {
    unsigned a = (unsigned)__cvta_generic_to_shared(p);
    asm volatile("ldmatrix.sync.aligned.m8n8.x2.trans.shared.b16 {%0,%1}, [%2];"
        : "=r"(r[0]), "=r"(r[1]) : "r"(a));
}
__device__ __forceinline__ void mma16816(float* c, const unsigned* a, const unsigned* b) {
    asm volatile("mma.sync.aligned.m16n8k16.row.col.f32.f16.f16.f32 "
        "{%0,%1,%2,%3}, {%4,%5,%6,%7}, {%8,%9}, {%0,%1,%2,%3};"
        : "+f"(c[0]), "+f"(c[1]), "+f"(c[2]), "+f"(c[3])
        : "r"(a[0]), "r"(a[1]), "r"(a[2]), "r"(a[3]), "r"(b[0]), "r"(b[1]));
}

// ---------------- graph build ----------------
__global__ void k_clear() {
    int i = blockIdx.x * blockDim.x + threadIdx.x;
    if (i < Nn * Nn / 128) ((uint4*)g_bitmap)[i] = make_uint4(0, 0, 0, 0);
    if (i < Nn) g_deg[i] = 0;
    if (i < 512) g_colsum1[i] = 0.f;
    if (i < NC) g_colsum2[i] = 0.f;
}

__global__ void k_dedup(const int* __restrict__ el) {   // 4 edges/thread
    int b = 4 * (blockIdx.x * blockDim.x + threadIdx.x);
    if (b >= Ee) return;
    int4 sv = *(const int4*)(el + b);
    int4 tv = *(const int4*)(el + Ee + b);
    int ss[4] = {sv.x, sv.y, sv.z, sv.w};
    int tt[4] = {tv.x, tv.y, tv.z, tv.w};
    unsigned old[4];
    #pragma unroll
    for (int q = 0; q < 4; q++) {
        unsigned idx = ((unsigned)ss[q] << 12) | (unsigned)tt[q];
        old[q] = atomicOr(&g_bitmap[idx >> 5], 1u << (idx & 31));
    }
    int4 rk;
    int* rkp = (int*)&rk;
    #pragma unroll
    for (int q = 0; q < 4; q++) {
        unsigned idx = ((unsigned)ss[q] << 12) | (unsigned)tt[q];
        bool isnew = !(old[q] & (1u << (idx & 31)));
        rkp[q] = isnew ? (atomicAdd(&g_deg[ss[q]], 1) + 1) : 0;
    }
    *(int4*)(g_rnk + b) = rk;
}

__global__ void k_scan() {   // 1 block, 1024 threads, warp-shuffle scan
    __shared__ int warpsum[32];
    int tid = threadIdx.x;
    int lane = tid & 31, wid = tid >> 5;
    int v0 = g_deg[4 * tid + 0];
    int v1 = g_deg[4 * tid + 1];
    int v2 = g_deg[4 * tid + 2];
    int v3 = g_deg[4 * tid + 3];
    int tot = v0 + v1 + v2 + v3;
    int s = tot;
    #pragma unroll
    for (int o = 1; o < 32; o <<= 1) {
        int t = __shfl_up_sync(0xffffffffu, s, o);
        if (lane >= o) s += t;
    }
    if (lane == 31) warpsum[wid] = s;
    __syncthreads();
    if (wid == 0) {
        int ws = warpsum[lane];
        #pragma unroll
        for (int o = 1; o < 32; o <<= 1) {
            int t = __shfl_up_sync(0xffffffffu, ws, o);
            if (lane >= o) ws += t;
        }
        warpsum[lane] = ws;
    }
    __syncthreads();
    int p = (wid ? warpsum[wid - 1] : 0) + s - tot;   // exclusive prefix
    g_rowptr[4 * tid + 0] = p; p += v0;
    g_rowptr[4 * tid + 1] = p; p += v1;
    g_rowptr[4 * tid + 2] = p; p += v2;
    g_rowptr[4 * tid + 3] = p; p += v3;
    if (tid == 1023) g_rowptr[Nn] = warpsum[31];
}

__global__ void k_scatter(const int* __restrict__ el) {  // atomic-free
    int b = 4 * (blockIdx.x * blockDim.x + threadIdx.x);
    if (b >= Ee) return;
    int4 sv = *(const int4*)(el + b);
    int4 tv = *(const int4*)(el + Ee + b);
    int4 rv = *(const int4*)(g_rnk + b);
    int ss[4] = {sv.x, sv.y, sv.z, sv.w};
    int tt[4] = {tv.x, tv.y, tv.z, tv.w};
    int rr[4] = {rv.x, rv.y, rv.z, rv.w};
    #pragma unroll
    for (int q = 0; q < 4; q++)
        if (rr[q]) g_col[g_rowptr[ss[q]] + rr[q] - 1] = tt[q];
}

// ---------------- fp32 -> (hi,lo) fp16 pre-split of A and Wcat ---------------
__global__ void k_tohalf(const float* __restrict__ A, const float* __restrict__ Wh) {
    int i = blockIdx.x * blockDim.x + threadIdx.x;   // float4 group
    const int NA4 = Nn * FIN / 4;
    if (i < NA4) {
        float4 v = ((const float4*)A)[i];
        __half h0 = __float2half_rn(v.x), h1 = __float2half_rn(v.y);
        __half h2 = __float2half_rn(v.z), h3 = __float2half_rn(v.w);
        ((__half2*)g_Ahi)[2 * i] = __halves2half2(h0, h1);
        ((__half2*)g_Ahi)[2 * i + 1] = __halves2half2(h2, h3);
        ((__half2*)g_Alo)[2 * i] = __halves2half2(
            __float2half_rn(v.x - __half2float(h0)), __float2half_rn(v.y - __half2float(h1)));
        ((__half2*)g_Alo)[2 * i + 1] = __halves2half2(
            __float2half_rn(v.z - __half2float(h2)), __float2half_rn(v.w - __half2float(h3)));
    } else if (i < NA4 + FIN * 512 / 4) {
        int j = (i - NA4) * 4;           // element index in Wcat [FIN][512]
        int k = j >> 9, c = j & 511;
        int hh = c >> 6, jj = c & 63;
        float4 v = *(const float4*)(Wh + hh * (FIN * HID) + k * HID + jj);
        __half h0 = __float2half_rn(v.x), h1 = __float2half_rn(v.y);
        __half h2 = __float2half_rn(v.z), h3 = __float2half_rn(v.w);
        __half2* dst_hi = (__half2*)(g_Whi + k * 512 + c);
        __half2* dst_lo = (__half2*)(g_Wlo + k * 512 + c);
        dst_hi[0] = __halves2half2(h0, h1);
        dst_hi[1] = __halves2half2(h2, h3);
        dst_lo[0] = __halves2half2(
            __float2half_rn(v.x - __half2float(h0)), __float2half_rn(v.y - __half2float(h1)));
        dst_lo[1] = __halves2half2(
            __float2half_rn(v.z - __half2float(h2)), __float2half_rn(v.w - __half2float(h3)));
    }
}

// ---------------- GEMM1 via fp16 tensor cores, 3-term split precision -------
#define BM 128
#define BN 128
#define BK 32
#define LDA 40
#define LDB 136

__global__ void __launch_bounds__(256) k_gemm1_mma() {
    __shared__ __half As_hi[BM][LDA], As_lo[BM][LDA];
    __shared__ __half Bs_hi[BK][LDB], Bs_lo[BK][LDB];
    int tid = threadIdx.x;
    int wid = tid >> 5, lane = tid & 31;
    int wm = wid & 1, wn = wid >> 1;          // warp tile: 64x32
    int row0 = blockIdx.y * BM, col0 = blockIdx.x * BN;

    int arow = tid >> 1, acol = (tid & 1) * 16;   // 16 halves of A per thread
    int bkrow = tid >> 3, bn = (tid & 7) * 16;    // 16 halves of B per thread
    const __half* aph = g_Ahi + (row0 + arow) * FIN + acol;
    const __half* apl = g_Alo + (row0 + arow) * FIN + acol;
    const __half* bph = g_Whi + bkrow * 512 + col0 + bn;
    const __half* bpl = g_Wlo + bkrow * 512 + col0 + bn;

    uint4 rah[2], ral[2], rbh[2], rbl[2];
    rah[0] = *(const uint4*)(aph);     rah[1] = *(const uint4*)(aph + 8);
    ral[0] = *(const uint4*)(apl);     ral[1] = *(const uint4*)(apl + 8);
    rbh[0] = *(const uint4*)(bph);     rbh[1] = *(const uint4*)(bph + 8);
    rbl[0] = *(const uint4*)(bpl);     rbl[1] = *(const uint4*)(bpl + 8);

    float acc[4][4][4];
    #pragma unroll
    for (int mi = 0; mi < 4; mi++)
        #pragma unroll
        for (int ni = 0; ni < 4; ni++)
            #pragma unroll
            for (int q = 0; q < 4; q++) acc[mi][ni][q] = 0.f;

    for (int k0 = 0; k0 < FIN; k0 += BK) {
        *(uint4*)&As_hi[arow][acol] = rah[0];
        *(uint4*)&As_hi[arow][acol + 8] = rah[1];
        *(uint4*)&As_lo[arow][acol] = ral[0];
        *(uint4*)&As_lo[arow][acol + 8] = ral[1];
        *(uint4*)&Bs_hi[bkrow][bn] = rbh[0];
        *(uint4*)&Bs_hi[bkrow][bn + 8] = rbh[1];
        *(uint4*)&Bs_lo[bkrow][bn] = rbl[0];
        *(uint4*)&Bs_lo[bkrow][bn + 8] = rbl[1];
        __syncthreads();
        if (k0 + BK < FIN) {
            rah[0] = *(const uint4*)(aph + k0 + BK);
            rah[1] = *(const uint4*)(aph + k0 + BK + 8);
            ral[0] = *(const uint4*)(apl + k0 + BK);
            ral[1] = *(const uint4*)(apl + k0 + BK + 8);
            rbh[0] = *(const uint4*)(bph + (k0 + BK) * 512);
            rbh[1] = *(const uint4*)(bph + (k0 + BK) * 512 + 8);
            rbl[0] = *(const uint4*)(bpl + (k0 + BK) * 512);
            rbl[1] = *(const uint4*)(bpl + (k0 + BK) * 512 + 8);
        }
        #pragma unroll
        for (int ks = 0; ks < BK; ks += 16) {
            unsigned afh[4][4], afl[4][4], bfh[4][2], bfl[4][2];
            #pragma unroll
            for (int mi = 0; mi < 4; mi++) {
                int r = wm * 64 + mi * 16 + (lane & 15);
                int c = ks + (lane >> 4) * 8;
                ldm_x4(afh[mi], &As_hi[r][c]);
                ldm_x4(afl[mi], &As_lo[r][c]);
            }
            #pragma unroll
            for (int ni = 0; ni < 4; ni++) {
                int kr = ks + (lane & 15);
                int nc = wn * 32 + ni * 8;
                ldm_x2t(bfh[ni], &Bs_hi[kr][nc]);
                ldm_x2t(bfl[ni], &Bs_lo[kr][nc]);
            }
            #pragma unroll
            for (int mi = 0; mi < 4; mi++)
                #pragma unroll
                for (int ni = 0; ni < 4; ni++) {
                    mma16816(acc[mi][ni], afh[mi], bfh[ni]);
                    mma16816(acc[mi][ni], afh[mi], bfl[ni]);
                    mma16816(acc[mi][ni], afl[mi], bfh[ni]);
                }
        }
        __syncthreads();
    }
    #pragma unroll
    for (int mi = 0; mi < 4; mi++)
        #pragma unroll
        for (int ni = 0; ni < 4; ni++) {
            int r = row0 + wm * 64 + mi * 16 + (lane >> 2);
            int c = col0 + wn * 32 + ni * 8 + (lane & 3) * 2;
            *(__half2*)(g_h1h + r * 512 + c) =
                __floats2half2_rn(acc[mi][ni][0], acc[mi][ni][1]);
            *(__half2*)(g_h1h + (r + 8) * 512 + c) =
                __floats2half2_rn(acc[mi][ni][2], acc[mi][ni][3]);
        }
}

// ---------------- per-node attention score halves, layer 1 (fp16 h) --------
__global__ void k_scores1(const float* __restrict__ a_heads) {
    int n = blockIdx.x;
    int h = threadIdx.x >> 5, lane = threadIdx.x & 31;
    const __half2* hp = (const __half2*)(g_h1h + n * 512 + h * HID);
    float2 v = __half22float2(hp[lane]);
    const float* ap = a_heads + h * 2 * HID;
    float p1 = v.x * ap[2 * lane] + v.y * ap[2 * lane + 1];
    float p2 = v.x * ap[64 + 2 * lane] + v.y * ap[64 + 2 * lane + 1];
    p1 = wredsum(p1);
    p2 = wredsum(p2);
    if (lane == 0) {
        g_s1[h * Nn + n] = p1;
        g_s2[h * Nn + n] = p2;
    }
}

__global__ void k_colmean1() {   // grid 64, block 256, half2 per thread
    int c2 = threadIdx.x;        // half2 index 0..255
    int r0 = blockIdx.x * 64;
    float s0 = 0.f, s1 = 0.f;
    #pragma unroll 4
    for (int r = 0; r < 64; r++) {
        float2 v = __half22float2(((const __half2*)(g_h1h + (r0 + r) * 512))[c2]);
        s0 += v.x; s1 += v.y;
    }
    atomicAdd(&g_colsum1[2 * c2], s0);
    atomicAdd(&g_colsum1[2 * c2 + 1], s1);
}

// ---------------- layer-1 softmax aggregation (+bias +elu) ----------------
__global__ void __launch_bounds__(256) k_agg1(const float* __restrict__ b_heads) {
    __shared__ float wbuf[8][132];
    __shared__ int   cbuf[8][132];
    int i = blockIdx.x;
    int h = threadIdx.x >> 5, lane = threadIdx.x & 31;
    int p0 = g_rowptr[i], p1 = g_rowptr[i + 1];
    int deg = p1 - p0;
    int c0 = h * HID + 2 * lane;
    float o0, o1;
    if (deg == 0) {
        o0 = g_colsum1[c0] * (1.f / Nn);
        o1 = g_colsum1[c0 + 1] * (1.f / Nn);
    } else if (deg <= 128) {
        float s1i = g_s1[h * Nn + i];
        const float* s2p = g_s2 + h * Nn;
        float m = -1e30f;
        for (int j = lane; j < deg; j += 32) {
            int t = g_col[p0 + j];
            cbuf[h][j] = t;
            float e = s1i + s2p[t];
            e = e > 0.f ? e : LALPHA * e;
            wbuf[h][j] = e;
            m = fmaxf(m, e);
        }
        m = wredmax(m);
        float ss = 0.f;
        for (int j = lane; j < deg; j += 32) {
            float w = expf(wbuf[h][j] - m);
            wbuf[h][j] = w;
            ss += w;
        }
        ss = wredsum(ss);
        __syncwarp();
        float inv = 1.f / ss;
        float a0 = 0.f, a1 = 0.f;
        const int pair = h * 32 + lane;
        #pragma unroll 4
        for (int j = 0; j < deg; j++) {
            int t = cbuf[h][j];
            float w = wbuf[h][j];
            float2 v = __half22float2(*((const __half2*)(g_h1h + t * 512) + pair));
            a0 = fmaf(w, v.x, a0);
            a1 = fmaf(w, v.y, a1);
        }
        o0 = a0 * inv; o1 = a1 * inv;
    } else {   // rare fallback
        float s1i = g_s1[h * Nn + i];
        const float* s2p = g_s2 + h * Nn;
        float m = -1e30f;
        for (int p = p0 + lane; p < p1; p += 32) {
            float e = s1i + s2p[g_col[p]];
            e = e > 0.f ? e : LALPHA * e;
            m = fmaxf(m, e);
        }
        m = wredmax(m);
        float ss = 0.f;
        for (int p = p0 + lane; p < p1; p += 32) {
            float e = s1i + s2p[g_col[p]];
            e = e > 0.f ? e : LALPHA * e;
            ss += expf(e - m);
        }
        ss = wredsum(ss);
        float inv = 1.f / ss;
        float a0 = 0.f, a1 = 0.f;
        const int pair = h * 32 + lane;
        for (int p = p0; p < p1; p++) {
            int t = g_col[p];
            float e = s1i + s2p[t];
            e = e > 0.f ? e : LALPHA * e;
            float w = expf(e - m) * inv;
            float2 v = __half22float2(*((const __half2*)(g_h1h + t * 512) + pair));
            a0 = fmaf(w, v.x, a0);
            a1 = fmaf(w, v.y, a1);
        }
        o0 = a0; o1 = a1;
    }
    o0 += b_heads[c0];
    o1 += b_heads[c0 + 1];
    o0 = o0 > 0.f ? o0 : expm1f(o0);   // elu
    o1 = o1 > 0.f ? o1 : expm1f(o1);
    g_x[i * 512 + c0] = o0;
    g_x[i * 512 + c0 + 1] = o1;
}

// ---------------- GEMM2 + fused layer-2 scores ----------------
#define LDW 516
__global__ void __launch_bounds__(256) k_gemm2(const float* __restrict__ Wout,
                                               const float* __restrict__ a_out) {
    __shared__ float WsT[NC][LDW];   // transposed, padded
    int tid = threadIdx.x;
    for (int j = tid; j < 512 * NC; j += 256) WsT[j & 15][j >> 4] = Wout[j];
    __syncthreads();
    int col = tid & 15, rs = tid >> 4;
    int row = blockIdx.x * 16 + rs;
    const float4* xp4 = (const float4*)(g_x + row * 512);
    const float4* wp4 = (const float4*)WsT[col];
    float a0 = 0.f, a1 = 0.f, a2 = 0.f, a3 = 0.f;
    #pragma unroll 8
    for (int k = 0; k < 128; k++) {
        float4 xv = xp4[k];
        float4 wv = wp4[k];
        a0 = fmaf(xv.x, wv.x, a0);
        a1 = fmaf(xv.y, wv.y, a1);
        a2 = fmaf(xv.z, wv.z, a2);
        a3 = fmaf(xv.w, wv.w, a3);
    }
    float v = (a0 + a1) + (a2 + a3);
    g_h2[row * NC + col] = v;
    // fused scores2
    float q1 = v * a_out[col];
    float q2 = v * a_out[16 + col];
    #pragma unroll
    for (int o = 8; o; o >>= 1) {
        q1 += __shfl_xor_sync(0xffffffffu, q1, o);
        q2 += __shfl_xor_sync(0xffffffffu, q2, o);
    }
    if (col == 0) { g_t1[row] = q1; g_t2[row] = q2; }
    atomicAdd(&g_colsum2[col], v);
}

// ---------------- layer-2 aggregation + log_softmax ----------------
__global__ void __launch_bounds__(256) k_agg2(const float* __restrict__ b_out,
                                              float* __restrict__ out) {
    __shared__ float wbuf[8][132];
    __shared__ int   cbuf[8][132];
    int wid = threadIdx.x >> 5, lane = threadIdx.x & 31;
    int i = blockIdx.x * 8 + wid;
    int p0 = g_rowptr[i], p1 = g_rowptr[i + 1];
    int deg = p1 - p0;
    float logit = 0.f;
    if (deg == 0) {
        if (lane < 16) logit = g_colsum2[lane] * (1.f / Nn) + b_out[lane];
    } else if (deg <= 128) {
        float t1i = g_t1[i];
        float m = -1e30f;
        for (int j = lane; j < deg; j += 32) {
            int t = g_col[p0 + j];
            cbuf[wid][j] = t;
            float e = t1i + g_t2[t];
            e = e > 0.f ? e : LALPHA * e;
            wbuf[wid][j] = e;
            m = fmaxf(m, e);
        }
        m = wredmax(m);
        float ss = 0.f;
        for (int j = lane; j < deg; j += 32) {
            float w = expf(wbuf[wid][j] - m);
            wbuf[wid][j] = w;
            ss += w;
        }
        ss = wredsum(ss);
        __syncwarp();
        float inv = 1.f / ss;
        float acc = 0.f;
        #pragma unroll 4
        for (int j = 0; j < deg; j++) {
            int t = cbuf[wid][j];
            float w = wbuf[wid][j];
            if (lane < 16) acc = fmaf(w, g_h2[t * NC + lane], acc);
        }
        if (lane < 16) logit = acc * inv + b_out[lane];
    } else {
        float t1i = g_t1[i];
        float m = -1e30f;
        for (int p = p0 + lane; p < p1; p += 32) {
            float e = t1i + g_t2[g_col[p]];
            e = e > 0.f ? e : LALPHA * e;
            m = fmaxf(m, e);
        }
        m = wredmax(m);
        float ss = 0.f;
        for (int p = p0 + lane; p < p1; p += 32) {
            float e = t1i + g_t2[g_col[p]];
            e = e > 0.f ? e : LALPHA * e;
            ss += expf(e - m);
        }
        ss = wredsum(ss);
        float inv = 1.f / ss;
        float acc = 0.f;
        for (int p = p0; p < p1; p++) {
            int t = g_col[p];
            float e = t1i + g_t2[t];
            e = e > 0.f ? e : LALPHA * e;
            float w = expf(e - m) * inv;
            if (lane < 16) acc = fmaf(w, g_h2[t * NC + lane], acc);
        }
        if (lane < 16) logit = acc + b_out[lane];
    }
    // log_softmax over 16 classes
    float lm = (lane < 16) ? logit : -1e30f;
    #pragma unroll
    for (int o = 8; o; o >>= 1) lm = fmaxf(lm, __shfl_xor_sync(0xffffffffu, lm, o));
    float es = (lane < 16) ? expf(logit - lm) : 0.f;
    #pragma unroll
    for (int o = 8; o; o >>= 1) es += __shfl_xor_sync(0xffffffffu, es, o);
    if (lane < 16) out[i * NC + lane] = logit - lm - logf(es);
}

// ---------------- launch ----------------
extern "C" void kernel_launch(void* const* d_in, const int* in_sizes, int n_in,
                              void* d_out, int out_size) {
    const float* features    = (const float*)d_in[0];
    const int* el            = (const int*)d_in[1];
    const float* W_heads     = (const float*)d_in[2];
    const float* a_heads     = (const float*)d_in[3];
    const float* b_heads     = (const float*)d_in[4];
    const float* W_out       = (const float*)d_in[5];
    const float* a_out       = (const float*)d_in[6];
    const float* b_out       = (const float*)d_in[7];
    float* out = (float*)d_out;

    k_clear<<<(Nn * Nn / 128 + 255) / 256, 256>>>();
    k_tohalf<<<(Nn * FIN / 4 + FIN * 512 / 4 + 255) / 256, 256>>>(features, W_heads);
    k_dedup<<<Ee / 1024, 256>>>(el);
    k_scan<<<1, 1024>>>();
    k_scatter<<<Ee / 1024, 256>>>(el);
    k_gemm1_mma<<<dim3(4, 32), 256>>>();
    k_scores1<<<Nn, 256>>>(a_heads);
    k_colmean1<<<64, 256>>>();
    k_agg1<<<Nn, 256>>>(b_heads);
    k_gemm2<<<Nn / 16, 256>>>(W_out, a_out);
    k_agg2<<<Nn / 8, 256>>>(b_out, out);
}

// round 6
// speedup vs baseline: 1.9717x; 1.0797x over previous
#include <cuda_runtime.h>
#include <cuda_fp16.h>

#define Nn 4096
#define Ee 262144
#define FIN 512
#define HID 64
#define NH 8
#define NC 16
#define LALPHA 0.2f

// ---------------- scratch (static __device__, no allocations) ----------------
__device__ unsigned g_bitmap[Nn * Nn / 32];   // 2MB dedup bitmap
__device__ int g_deg[Nn];
__device__ int g_rowptr[Nn + 1];
__device__ int g_rnk[Ee];                     // rank+1 within row, 0 = duplicate
__device__ int g_col[Ee];
__device__ __half g_Ahi[Nn * FIN], g_Alo[Nn * FIN];     // pre-split features
__device__ __half g_Whi[FIN * 512], g_Wlo[FIN * 512];   // pre-split Wcat
__device__ __half g_h1h[Nn * 512];            // layer1 h fp16 (4MB)
__device__ float g_x[Nn * 512];               // elu(att@h + b) concat (8MB)
__device__ float g_s1[NH * Nn];
__device__ float g_s2[NH * Nn];
__device__ float g_colsum1[512];
__device__ float g_h2[Nn * NC];
__device__ float g_t1[Nn];
__device__ float g_t2[Nn];
__device__ float g_colsum2[NC];

// ---------------- helpers ----------------
__device__ __forceinline__ float wredsum(float v) {
    #pragma unroll
    for (int o = 16; o; o >>= 1) v += __shfl_xor_sync(0xffffffffu, v, o);
    return v;
}
__device__ __forceinline__ float wredmax(float v) {
    #pragma unroll
    for (int o = 16; o; o >>= 1) v = fmaxf(v, __shfl_xor_sync(0xffffffffu, v, o));
    return v;
}

__device__ __forceinline__ void ldm_x4(unsigned* r, const void* p) {
    unsigned a = (unsigned)__cvta_generic_to_shared(p);
    asm volatile("ldmatrix.sync.aligned.m8n8.x4.shared.b16 {%0,%1,%2,%3}, [%4];"
        : "=r"(r[0]), "=r"(r[1]), "=r"(r[2]), "=r"(r[3]) : "r"(a));
}
__device__ __forceinline__ void ldm_x2t(unsigned* r, const void* p) {
    unsigned a = (unsigned)__cvta_generic_to_shared(p);
    asm volatile("ldmatrix.sync.aligned.m8n8.x2.trans.shared.b16 {%0,%1}, [%2];"
        : "=r"(r[0]), "=r"(r[1]) : "r"(a));
}
__device__ __forceinline__ void mma16816(float* c, const unsigned* a, const unsigned* b) {
    asm volatile("mma.sync.aligned.m16n8k16.row.col.f32.f16.f16.f32 "
        "{%0,%1,%2,%3}, {%4,%5,%6,%7}, {%8,%9}, {%0,%1,%2,%3};"
        : "+f"(c[0]), "+f"(c[1]), "+f"(c[2]), "+f"(c[3])
        : "r"(a[0]), "r"(a[1]), "r"(a[2]), "r"(a[3]), "r"(b[0]), "r"(b[1]));
}

// ---------------- graph build (stream 2) ----------------
__global__ void k_clear_graph() {
    int i = blockIdx.x * blockDim.x + threadIdx.x;
    if (i < Nn * Nn / 128) ((uint4*)g_bitmap)[i] = make_uint4(0, 0, 0, 0);
    if (i < Nn) g_deg[i] = 0;
}

__global__ void k_clear_sums() {
    int i = threadIdx.x;
    if (i < 512) g_colsum1[i] = 0.f;
    if (i < NC) g_colsum2[i] = 0.f;
}

__global__ void k_dedup(const int* __restrict__ el) {   // 4 edges/thread
    int b = 4 * (blockIdx.x * blockDim.x + threadIdx.x);
    if (b >= Ee) return;
    int4 sv = *(const int4*)(el + b);
    int4 tv = *(const int4*)(el + Ee + b);
    int ss[4] = {sv.x, sv.y, sv.z, sv.w};
    int tt[4] = {tv.x, tv.y, tv.z, tv.w};
    unsigned old[4];
    #pragma unroll
    for (int q = 0; q < 4; q++) {
        unsigned idx = ((unsigned)ss[q] << 12) | (unsigned)tt[q];
        old[q] = atomicOr(&g_bitmap[idx >> 5], 1u << (idx & 31));
    }
    int4 rk;
    int* rkp = (int*)&rk;
    #pragma unroll
    for (int q = 0; q < 4; q++) {
        unsigned idx = ((unsigned)ss[q] << 12) | (unsigned)tt[q];
        bool isnew = !(old[q] & (1u << (idx & 31)));
        rkp[q] = isnew ? (atomicAdd(&g_deg[ss[q]], 1) + 1) : 0;
    }
    *(int4*)(g_rnk + b) = rk;
}

__global__ void k_scan() {   // 1 block, 1024 threads, warp-shuffle scan
    __shared__ int warpsum[32];
    int tid = threadIdx.x;
    int lane = tid & 31, wid = tid >> 5;
    int v0 = g_deg[4 * tid + 0];
    int v1 = g_deg[4 * tid + 1];
    int v2 = g_deg[4 * tid + 2];
    int v3 = g_deg[4 * tid + 3];
    int tot = v0 + v1 + v2 + v3;
    int s = tot;
    #pragma unroll
    for (int o = 1; o < 32; o <<= 1) {
        int t = __shfl_up_sync(0xffffffffu, s, o);
        if (lane >= o) s += t;
    }
    if (lane == 31) warpsum[wid] = s;
    __syncthreads();
    if (wid == 0) {
        int ws = warpsum[lane];
        #pragma unroll
        for (int o = 1; o < 32; o <<= 1) {
            int t = __shfl_up_sync(0xffffffffu, ws, o);
            if (lane >= o) ws += t;
        }
        warpsum[lane] = ws;
    }
    __syncthreads();
    int p = (wid ? warpsum[wid - 1] : 0) + s - tot;   // exclusive prefix
    g_rowptr[4 * tid + 0] = p; p += v0;
    g_rowptr[4 * tid + 1] = p; p += v1;
    g_rowptr[4 * tid + 2] = p; p += v2;
    g_rowptr[4 * tid + 3] = p; p += v3;
    if (tid == 1023) g_rowptr[Nn] = warpsum[31];
}

__global__ void k_scatter(const int* __restrict__ el) {  // atomic-free
    int b = 4 * (blockIdx.x * blockDim.x + threadIdx.x);
    if (b >= Ee) return;
    int4 sv = *(const int4*)(el + b);
    int4 tv = *(const int4*)(el + Ee + b);
    int4 rv = *(const int4*)(g_rnk + b);
    int ss[4] = {sv.x, sv.y, sv.z, sv.w};
    int tt[4] = {tv.x, tv.y, tv.z, tv.w};
    int rr[4] = {rv.x, rv.y, rv.z, rv.w};
    #pragma unroll
    for (int q = 0; q < 4; q++)
        if (rr[q]) g_col[g_rowptr[ss[q]] + rr[q] - 1] = tt[q];
}

// ---------------- fp32 -> (hi,lo) fp16 pre-split of A and Wcat ---------------
__global__ void k_tohalf(const float* __restrict__ A, const float* __restrict__ Wh) {
    int i = blockIdx.x * blockDim.x + threadIdx.x;   // float4 group
    const int NA4 = Nn * FIN / 4;
    if (i < NA4) {
        float4 v = ((const float4*)A)[i];
        __half h0 = __float2half_rn(v.x), h1 = __float2half_rn(v.y);
        __half h2 = __float2half_rn(v.z), h3 = __float2half_rn(v.w);
        ((__half2*)g_Ahi)[2 * i] = __halves2half2(h0, h1);
        ((__half2*)g_Ahi)[2 * i + 1] = __halves2half2(h2, h3);
        ((__half2*)g_Alo)[2 * i] = __halves2half2(
            __float2half_rn(v.x - __half2float(h0)), __float2half_rn(v.y - __half2float(h1)));
        ((__half2*)g_Alo)[2 * i + 1] = __halves2half2(
            __float2half_rn(v.z - __half2float(h2)), __float2half_rn(v.w - __half2float(h3)));
    } else if (i < NA4 + FIN * 512 / 4) {
        int j = (i - NA4) * 4;           // element index in Wcat [FIN][512]
        int k = j >> 9, c = j & 511;
        int hh = c >> 6, jj = c & 63;
        float4 v = *(const float4*)(Wh + hh * (FIN * HID) + k * HID + jj);
        __half h0 = __float2half_rn(v.x), h1 = __float2half_rn(v.y);
        __half h2 = __float2half_rn(v.z), h3 = __float2half_rn(v.w);
        __half2* dst_hi = (__half2*)(g_Whi + k * 512 + c);
        __half2* dst_lo = (__half2*)(g_Wlo + k * 512 + c);
        dst_hi[0] = __halves2half2(h0, h1);
        dst_hi[1] = __halves2half2(h2, h3);
        dst_lo[0] = __halves2half2(
            __float2half_rn(v.x - __half2float(h0)), __float2half_rn(v.y - __half2float(h1)));
        dst_lo[1] = __halves2half2(
            __float2half_rn(v.z - __half2float(h2)), __float2half_rn(v.w - __half2float(h3)));
    }
}

// ---------------- GEMM1 via fp16 tensor cores, 3-term split precision -------
#define BM 128
#define BN 128
#define BK 32
#define LDA 40
#define LDB 136

__global__ void __launch_bounds__(256) k_gemm1_mma() {
    __shared__ __half As_hi[BM][LDA], As_lo[BM][LDA];
    __shared__ __half Bs_hi[BK][LDB], Bs_lo[BK][LDB];
    int tid = threadIdx.x;
    int wid = tid >> 5, lane = tid & 31;
    int wm = wid & 1, wn = wid >> 1;          // warp tile: 64x32
    int row0 = blockIdx.y * BM, col0 = blockIdx.x * BN;

    int arow = tid >> 1, acol = (tid & 1) * 16;
    int bkrow = tid >> 3, bn = (tid & 7) * 16;
    const __half* aph = g_Ahi + (row0 + arow) * FIN + acol;
    const __half* apl = g_Alo + (row0 + arow) * FIN + acol;
    const __half* bph = g_Whi + bkrow * 512 + col0 + bn;
    const __half* bpl = g_Wlo + bkrow * 512 + col0 + bn;

    uint4 rah[2], ral[2], rbh[2], rbl[2];
    rah[0] = *(const uint4*)(aph);     rah[1] = *(const uint4*)(aph + 8);
    ral[0] = *(const uint4*)(apl);     ral[1] = *(const uint4*)(apl + 8);
    rbh[0] = *(const uint4*)(bph);     rbh[1] = *(const uint4*)(bph + 8);
    rbl[0] = *(const uint4*)(bpl);     rbl[1] = *(const uint4*)(bpl + 8);

    float acc[4][4][4];
    #pragma unroll
    for (int mi = 0; mi < 4; mi++)
        #pragma unroll
        for (int ni = 0; ni < 4; ni++)
            #pragma unroll
            for (int q = 0; q < 4; q++) acc[mi][ni][q] = 0.f;

    for (int k0 = 0; k0 < FIN; k0 += BK) {
        *(uint4*)&As_hi[arow][acol] = rah[0];
        *(uint4*)&As_hi[arow][acol + 8] = rah[1];
        *(uint4*)&As_lo[arow][acol] = ral[0];
        *(uint4*)&As_lo[arow][acol + 8] = ral[1];
        *(uint4*)&Bs_hi[bkrow][bn] = rbh[0];
        *(uint4*)&Bs_hi[bkrow][bn + 8] = rbh[1];
        *(uint4*)&Bs_lo[bkrow][bn] = rbl[0];
        *(uint4*)&Bs_lo[bkrow][bn + 8] = rbl[1];
        __syncthreads();
        if (k0 + BK < FIN) {
            rah[0] = *(const uint4*)(aph + k0 + BK);
            rah[1] = *(const uint4*)(aph + k0 + BK + 8);
            ral[0] = *(const uint4*)(apl + k0 + BK);
            ral[1] = *(const uint4*)(apl + k0 + BK + 8);
            rbh[0] = *(const uint4*)(bph + (k0 + BK) * 512);
            rbh[1] = *(const uint4*)(bph + (k0 + BK) * 512 + 8);
            rbl[0] = *(const uint4*)(bpl + (k0 + BK) * 512);
            rbl[1] = *(const uint4*)(bpl + (k0 + BK) * 512 + 8);
        }
        #pragma unroll
        for (int ks = 0; ks < BK; ks += 16) {
            unsigned afh[4][4], afl[4][4], bfh[4][2], bfl[4][2];
            #pragma unroll
            for (int mi = 0; mi < 4; mi++) {
                int r = wm * 64 + mi * 16 + (lane & 15);
                int c = ks + (lane >> 4) * 8;
                ldm_x4(afh[mi], &As_hi[r][c]);
                ldm_x4(afl[mi], &As_lo[r][c]);
            }
            #pragma unroll
            for (int ni = 0; ni < 4; ni++) {
                int kr = ks + (lane & 15);
                int nc = wn * 32 + ni * 8;
                ldm_x2t(bfh[ni], &Bs_hi[kr][nc]);
                ldm_x2t(bfl[ni], &Bs_lo[kr][nc]);
            }
            #pragma unroll
            for (int mi = 0; mi < 4; mi++)
                #pragma unroll
                for (int ni = 0; ni < 4; ni++) {
                    mma16816(acc[mi][ni], afh[mi], bfh[ni]);
                    mma16816(acc[mi][ni], afh[mi], bfl[ni]);
                    mma16816(acc[mi][ni], afl[mi], bfh[ni]);
                }
        }
        __syncthreads();
    }
    #pragma unroll
    for (int mi = 0; mi < 4; mi++)
        #pragma unroll
        for (int ni = 0; ni < 4; ni++) {
            int r = row0 + wm * 64 + mi * 16 + (lane >> 2);
            int c = col0 + wn * 32 + ni * 8 + (lane & 3) * 2;
            *(__half2*)(g_h1h + r * 512 + c) =
                __floats2half2_rn(acc[mi][ni][0], acc[mi][ni][1]);
            *(__half2*)(g_h1h + (r + 8) * 512 + c) =
                __floats2half2_rn(acc[mi][ni][2], acc[mi][ni][3]);
        }
}

// ---------------- per-node attention score halves, layer 1 (fp16 h) --------
__global__ void k_scores1(const float* __restrict__ a_heads) {
    int n = blockIdx.x;
    int h = threadIdx.x >> 5, lane = threadIdx.x & 31;
    const __half2* hp = (const __half2*)(g_h1h + n * 512 + h * HID);
    float2 v = __half22float2(hp[lane]);
    const float* ap = a_heads + h * 2 * HID;
    float p1 = v.x * ap[2 * lane] + v.y * ap[2 * lane + 1];
    float p2 = v.x * ap[64 + 2 * lane] + v.y * ap[64 + 2 * lane + 1];
    p1 = wredsum(p1);
    p2 = wredsum(p2);
    if (lane == 0) {
        g_s1[h * Nn + n] = p1;
        g_s2[h * Nn + n] = p2;
    }
}

__global__ void k_colmean1() {   // grid 64, block 256, half2 per thread
    int c2 = threadIdx.x;        // half2 index 0..255
    int r0 = blockIdx.x * 64;
    float s0 = 0.f, s1 = 0.f;
    #pragma unroll 4
    for (int r = 0; r < 64; r++) {
        float2 v = __half22float2(((const __half2*)(g_h1h + (r0 + r) * 512))[c2]);
        s0 += v.x; s1 += v.y;
    }
    atomicAdd(&g_colsum1[2 * c2], s0);
    atomicAdd(&g_colsum1[2 * c2 + 1], s1);
}

// ---------------- layer-1 softmax aggregation (+bias +elu) ----------------
__global__ void __launch_bounds__(256) k_agg1(const float* __restrict__ b_heads) {
    __shared__ float wbuf[8][132];
    __shared__ int   cbuf[8][132];
    int i = blockIdx.x;
    int h = threadIdx.x >> 5, lane = threadIdx.x & 31;
    int p0 = g_rowptr[i], p1 = g_rowptr[i + 1];
    int deg = p1 - p0;
    int c0 = h * HID + 2 * lane;
    float o0, o1;
    if (deg == 0) {
        o0 = g_colsum1[c0] * (1.f / Nn);
        o1 = g_colsum1[c0 + 1] * (1.f / Nn);
    } else if (deg <= 128) {
        float s1i = g_s1[h * Nn + i];
        const float* s2p = g_s2 + h * Nn;
        float m = -1e30f;
        for (int j = lane; j < deg; j += 32) {
            int t = g_col[p0 + j];
            cbuf[h][j] = t;
            float e = s1i + s2p[t];
            e = e > 0.f ? e : LALPHA * e;
            wbuf[h][j] = e;
            m = fmaxf(m, e);
        }
        m = wredmax(m);
        float ss = 0.f;
        for (int j = lane; j < deg; j += 32) {
            float w = expf(wbuf[h][j] - m);
            wbuf[h][j] = w;
            ss += w;
        }
        ss = wredsum(ss);
        __syncwarp();
        float inv = 1.f / ss;
        float a0 = 0.f, a1 = 0.f;
        const int pair = h * 32 + lane;
        #pragma unroll 8
        for (int j = 0; j < deg; j++) {
            int t = cbuf[h][j];
            float w = wbuf[h][j];
            float2 v = __half22float2(*((const __half2*)(g_h1h + t * 512) + pair));
            a0 = fmaf(w, v.x, a0);
            a1 = fmaf(w, v.y, a1);
        }
        o0 = a0 * inv; o1 = a1 * inv;
    } else {   // rare fallback
        float s1i = g_s1[h * Nn + i];
        const float* s2p = g_s2 + h * Nn;
        float m = -1e30f;
        for (int p = p0 + lane; p < p1; p += 32) {
            float e = s1i + s2p[g_col[p]];
            e = e > 0.f ? e : LALPHA * e;
            m = fmaxf(m, e);
        }
        m = wredmax(m);
        float ss = 0.f;
        for (int p = p0 + lane; p < p1; p += 32) {
            float e = s1i + s2p[g_col[p]];
            e = e > 0.f ? e : LALPHA * e;
            ss += expf(e - m);
        }
        ss = wredsum(ss);
        float inv = 1.f / ss;
        float a0 = 0.f, a1 = 0.f;
        const int pair = h * 32 + lane;
        for (int p = p0; p < p1; p++) {
            int t = g_col[p];
            float e = s1i + s2p[t];
            e = e > 0.f ? e : LALPHA * e;
            float w = expf(e - m) * inv;
            float2 v = __half22float2(*((const __half2*)(g_h1h + t * 512) + pair));
            a0 = fmaf(w, v.x, a0);
            a1 = fmaf(w, v.y, a1);
        }
        o0 = a0; o1 = a1;
    }
    o0 += b_heads[c0];
    o1 += b_heads[c0 + 1];
    o0 = o0 > 0.f ? o0 : expm1f(o0);   // elu
    o1 = o1 > 0.f ? o1 : expm1f(o1);
    g_x[i * 512 + c0] = o0;
    g_x[i * 512 + c0 + 1] = o1;
}

// ---------------- GEMM2 + fused layer-2 scores ----------------
#define LDW 516
__global__ void __launch_bounds__(256) k_gemm2(const float* __restrict__ Wout,
                                               const float* __restrict__ a_out) {
    __shared__ float WsT[NC][LDW];   // transposed, padded
    int tid = threadIdx.x;
    for (int j = tid; j < 512 * NC; j += 256) WsT[j & 15][j >> 4] = Wout[j];
    __syncthreads();
    int col = tid & 15, rs = tid >> 4;
    int row = blockIdx.x * 16 + rs;
    const float4* xp4 = (const float4*)(g_x + row * 512);
    const float4* wp4 = (const float4*)WsT[col];
    float a0 = 0.f, a1 = 0.f, a2 = 0.f, a3 = 0.f;
    #pragma unroll 8
    for (int k = 0; k < 128; k++) {
        float4 xv = xp4[k];
        float4 wv = wp4[k];
        a0 = fmaf(xv.x, wv.x, a0);
        a1 = fmaf(xv.y, wv.y, a1);
        a2 = fmaf(xv.z, wv.z, a2);
        a3 = fmaf(xv.w, wv.w, a3);
    }
    float v = (a0 + a1) + (a2 + a3);
    g_h2[row * NC + col] = v;
    // fused scores2
    float q1 = v * a_out[col];
    float q2 = v * a_out[16 + col];
    #pragma unroll
    for (int o = 8; o; o >>= 1) {
        q1 += __shfl_xor_sync(0xffffffffu, q1, o);
        q2 += __shfl_xor_sync(0xffffffffu, q2, o);
    }
    if (col == 0) { g_t1[row] = q1; g_t2[row] = q2; }
    atomicAdd(&g_colsum2[col], v);
}

// ---------------- layer-2 aggregation + log_softmax ----------------
__global__ void __launch_bounds__(256) k_agg2(const float* __restrict__ b_out,
                                              float* __restrict__ out) {
    __shared__ float wbuf[8][132];
    __shared__ int   cbuf[8][132];
    int wid = threadIdx.x >> 5, lane = threadIdx.x & 31;
    int i = blockIdx.x * 8 + wid;
    int p0 = g_rowptr[i], p1 = g_rowptr[i + 1];
    int deg = p1 - p0;
    float logit = 0.f;
    if (deg == 0) {
        if (lane < 16) logit = g_colsum2[lane] * (1.f / Nn) + b_out[lane];
    } else if (deg <= 128) {
        float t1i = g_t1[i];
        float m = -1e30f;
        for (int j = lane; j < deg; j += 32) {
            int t = g_col[p0 + j];
            cbuf[wid][j] = t;
            float e = t1i + g_t2[t];
            e = e > 0.f ? e : LALPHA * e;
            wbuf[wid][j] = e;
            m = fmaxf(m, e);
        }
        m = wredmax(m);
        float ss = 0.f;
        for (int j = lane; j < deg; j += 32) {
            float w = expf(wbuf[wid][j] - m);
            wbuf[wid][j] = w;
            ss += w;
        }
        ss = wredsum(ss);
        __syncwarp();
        float inv = 1.f / ss;
        float acc = 0.f;
        #pragma unroll 4
        for (int j = 0; j < deg; j++) {
            int t = cbuf[wid][j];
            float w = wbuf[wid][j];
            if (lane < 16) acc = fmaf(w, g_h2[t * NC + lane], acc);
        }
        if (lane < 16) logit = acc * inv + b_out[lane];
    } else {
        float t1i = g_t1[i];
        float m = -1e30f;
        for (int p = p0 + lane; p < p1; p += 32) {
            float e = t1i + g_t2[g_col[p]];
            e = e > 0.f ? e : LALPHA * e;
            m = fmaxf(m, e);
        }
        m = wredmax(m);
        float ss = 0.f;
        for (int p = p0 + lane; p < p1; p += 32) {
            float e = t1i + g_t2[g_col[p]];
            e = e > 0.f ? e : LALPHA * e;
            ss += expf(e - m);
        }
        ss = wredsum(ss);
        float inv = 1.f / ss;
        float acc = 0.f;
        for (int p = p0; p < p1; p++) {
            int t = g_col[p];
            float e = t1i + g_t2[t];
            e = e > 0.f ? e : LALPHA * e;
            float w = expf(e - m) * inv;
            if (lane < 16) acc = fmaf(w, g_h2[t * NC + lane], acc);
        }
        if (lane < 16) logit = acc + b_out[lane];
    }
    // log_softmax over 16 classes
    float lm = (lane < 16) ? logit : -1e30f;
    #pragma unroll
    for (int o = 8; o; o >>= 1) lm = fmaxf(lm, __shfl_xor_sync(0xffffffffu, lm, o));
    float es = (lane < 16) ? expf(logit - lm) : 0.f;
    #pragma unroll
    for (int o = 8; o; o >>= 1) es += __shfl_xor_sync(0xffffffffu, es, o);
    if (lane < 16) out[i * NC + lane] = logit - lm - logf(es);
}

// ---------------- side stream (created once, host resources only) ----------
struct SideStream {
    cudaStream_t s2;
    cudaEvent_t eFork, eJoin;
    SideStream() {
        cudaStreamCreateWithFlags(&s2, cudaStreamNonBlocking);
        cudaEventCreateWithFlags(&eFork, cudaEventDisableTiming);
        cudaEventCreateWithFlags(&eJoin, cudaEventDisableTiming);
    }
};
static SideStream g_ss;

// ---------------- launch ----------------
extern "C" void kernel_launch(void* const* d_in, const int* in_sizes, int n_in,
                              void* d_out, int out_size) {
    const float* features    = (const float*)d_in[0];
    const int* el            = (const int*)d_in[1];
    const float* W_heads     = (const float*)d_in[2];
    const float* a_heads     = (const float*)d_in[3];
    const float* b_heads     = (const float*)d_in[4];
    const float* W_out       = (const float*)d_in[5];
    const float* a_out       = (const float*)d_in[6];
    const float* b_out       = (const float*)d_in[7];
    float* out = (float*)d_out;

    // fork: graph-build chain on side stream
    cudaEventRecord(g_ss.eFork, 0);
    cudaStreamWaitEvent(g_ss.s2, g_ss.eFork, 0);
    k_clear_graph<<<(Nn * Nn / 128 + 255) / 256, 256, 0, g_ss.s2>>>();
    k_dedup<<<Ee / 1024, 256, 0, g_ss.s2>>>(el);
    k_scan<<<1, 1024, 0, g_ss.s2>>>();
    k_scatter<<<Ee / 1024, 256, 0, g_ss.s2>>>(el);
    cudaEventRecord(g_ss.eJoin, g_ss.s2);

    // main chain: compute
    k_clear_sums<<<1, 512>>>();
    k_tohalf<<<(Nn * FIN / 4 + FIN * 512 / 4 + 255) / 256, 256>>>(features, W_heads);
    k_gemm1_mma<<<dim3(4, 32), 256>>>();
    k_scores1<<<Nn, 256>>>(a_heads);
    k_colmean1<<<64, 256>>>();

    // join, then the dependent tail
    cudaStreamWaitEvent(0, g_ss.eJoin, 0);
    k_agg1<<<Nn, 256>>>(b_heads);
    k_gemm2<<<Nn / 16, 256>>>(W_out, a_out);
    k_agg2<<<Nn / 8, 256>>>(b_out, out);
}